// round 6
// baseline (speedup 1.0000x reference)
#include <cuda_runtime.h>
#include <math.h>
#include <stdint.h>

// Problem constants
#define Bv 2
#define Tv 8
#define Nv 576
#define Cv 1024
#define Hv 16
#define HDv 64
#define TNv (Tv * Nv)       // 4608
#define Mrows (Bv * TNv)    // 9216

// Scratch (device globals — no runtime allocation allowed)
__device__ float g_q[(size_t)Mrows * Cv];
__device__ float g_k[(size_t)Mrows * Cv];
__device__ float g_v[(size_t)Mrows * Cv];
__device__ float g_o[(size_t)Mrows * Cv];

// ---------------------------------------------------------------------------
// tf32 helpers
// ---------------------------------------------------------------------------
__device__ __forceinline__ unsigned tf32r(float x) {
    unsigned r;
    asm("cvt.rna.tf32.f32 %0, %1;" : "=r"(r) : "f"(x));
    return r;
}

__device__ __forceinline__ void mma8(float d[4], const unsigned a[4],
                                     const unsigned b[2]) {
    asm volatile(
        "mma.sync.aligned.m16n8k8.row.col.f32.tf32.tf32.f32 "
        "{%0,%1,%2,%3},{%4,%5,%6,%7},{%8,%9},{%0,%1,%2,%3};"
        : "+f"(d[0]), "+f"(d[1]), "+f"(d[2]), "+f"(d[3])
        : "r"(a[0]), "r"(a[1]), "r"(a[2]), "r"(a[3]), "r"(b[0]), "r"(b[1]));
}

// ---------------------------------------------------------------------------
// NT GEMM via tf32 mma (round-3 version, proven @1465us).
// C[m,n] = sum_k A[m,k] * W[n,k] (+ bias[n])
// ---------------------------------------------------------------------------
__global__ __launch_bounds__(256) void gemm_tf32(
    const float* __restrict__ A, const float* __restrict__ W,
    float* __restrict__ Cout, const float* __restrict__ bias)
{
    __shared__ unsigned As[16 * 136];
    __shared__ unsigned Bs[16 * 136];

    const int t = threadIdx.x;
    const int lane = t & 31;
    const int w = t >> 5;
    const int gid = lane >> 2, tig = lane & 3;
    const int wm = (w >> 2) * 64, wn = (w & 3) * 32;
    const int m0 = blockIdx.y * 128, n0 = blockIdx.x * 128;

    const int row0 = t >> 2;          // 0..63
    const int kq = (t & 3) * 4;       // 0,4,8,12
    const int cstS = (t & 3) << 3;    // ((k>>2)&3)<<3 for k = kq+jj

    const float* Ap0 = A + (size_t)(m0 + row0) * Cv + kq;
    const float* Ap1 = A + (size_t)(m0 + 64 + row0) * Cv + kq;
    const float* Wp0 = W + (size_t)(n0 + row0) * Cv + kq;
    const float* Wp1 = W + (size_t)(n0 + 64 + row0) * Cv + kq;

    float acc[4][4][4];
#pragma unroll
    for (int mt = 0; mt < 4; mt++)
#pragma unroll
        for (int nt = 0; nt < 4; nt++)
#pragma unroll
            for (int r = 0; r < 4; r++) acc[mt][nt][r] = 0.0f;

    float4 ra0 = *(const float4*)Ap0;
    float4 ra1 = *(const float4*)Ap1;
    float4 rb0 = *(const float4*)Wp0;
    float4 rb1 = *(const float4*)Wp1;

    for (int k0 = 0; k0 < Cv; k0 += 16) {
        __syncthreads();
        {
            float va0[4] = {ra0.x, ra0.y, ra0.z, ra0.w};
            float va1[4] = {ra1.x, ra1.y, ra1.z, ra1.w};
            float vb0[4] = {rb0.x, rb0.y, rb0.z, rb0.w};
            float vb1[4] = {rb1.x, rb1.y, rb1.z, rb1.w};
#pragma unroll
            for (int jj = 0; jj < 4; jj++) {
                int kr = (kq + jj) * 136;
                As[kr + (row0 ^ cstS)]        = tf32r(va0[jj]);
                As[kr + ((row0 + 64) ^ cstS)] = tf32r(va1[jj]);
                Bs[kr + (row0 ^ cstS)]        = tf32r(vb0[jj]);
                Bs[kr + ((row0 + 64) ^ cstS)] = tf32r(vb1[jj]);
            }
        }
        __syncthreads();
        if (k0 + 16 < Cv) {
            ra0 = *(const float4*)(Ap0 + k0 + 16);
            ra1 = *(const float4*)(Ap1 + k0 + 16);
            rb0 = *(const float4*)(Wp0 + k0 + 16);
            rb1 = *(const float4*)(Wp1 + k0 + 16);
        }
#pragma unroll
        for (int kk = 0; kk < 2; kk++) {
            const int kb = kk * 8;
            const int c0 = ((kb >> 2) & 3) << 3;
            const int c1 = (((kb + 4) >> 2) & 3) << 3;
            const int kr0 = (kb + tig) * 136;
            const int kr1 = (kb + tig + 4) * 136;
            unsigned a[4][4], bb[4][2];
#pragma unroll
            for (int mt = 0; mt < 4; mt++) {
                int m = wm + mt * 16 + gid;
                a[mt][0] = As[kr0 + (m ^ c0)];
                a[mt][1] = As[kr0 + ((m + 8) ^ c0)];
                a[mt][2] = As[kr1 + (m ^ c1)];
                a[mt][3] = As[kr1 + ((m + 8) ^ c1)];
            }
#pragma unroll
            for (int nt = 0; nt < 4; nt++) {
                int n = wn + nt * 8 + gid;
                bb[nt][0] = Bs[kr0 + (n ^ c0)];
                bb[nt][1] = Bs[kr1 + (n ^ c1)];
            }
#pragma unroll
            for (int mt = 0; mt < 4; mt++)
#pragma unroll
                for (int nt = 0; nt < 4; nt++)
                    mma8(acc[mt][nt], a[mt], bb[nt]);
        }
    }

#pragma unroll
    for (int mt = 0; mt < 4; mt++) {
        int r = m0 + wm + mt * 16 + gid;
#pragma unroll
        for (int nt = 0; nt < 4; nt++) {
            int c = n0 + wn + nt * 8 + tig * 2;
            float b0v = bias ? bias[c] : 0.0f;
            float b1v = bias ? bias[c + 1] : 0.0f;
            float2 v0, v1;
            v0.x = acc[mt][nt][0] + b0v;
            v0.y = acc[mt][nt][1] + b1v;
            v1.x = acc[mt][nt][2] + b0v;
            v1.y = acc[mt][nt][3] + b1v;
            *(float2*)(Cout + (size_t)r * Cv + c) = v0;
            *(float2*)(Cout + (size_t)(r + 8) * Cv + c) = v1;
        }
    }
}

// ---------------------------------------------------------------------------
// RoPE (in-place on q and k, token-major [Mrows,1024] layout).
// ---------------------------------------------------------------------------
__global__ __launch_bounds__(256) void rope_kernel(
    const float* __restrict__ fcos, const float* __restrict__ fsin)
{
    const long total = (long)Mrows * 512;
    long gid = (long)blockIdx.x * blockDim.x + threadIdx.x;
    if (gid >= 2 * total) return;
    float* arr = (gid < total) ? g_q : g_k;
    long id = (gid < total) ? gid : (gid - total);

    int m = (int)(id / 512);
    int p = (int)(id % 512);
    int col = p * 2;
    int d = col & 63;
    int s = m % TNv;

    float c0 = fcos[(size_t)s * HDv + d];
    float c1 = fcos[(size_t)s * HDv + d + 1];
    float s0 = fsin[(size_t)s * HDv + d];
    float s1 = fsin[(size_t)s * HDv + d + 1];

    float2 x = *(float2*)(arr + (size_t)m * Cv + col);
    float2 y;
    y.x = x.x * c0 - x.y * s0;
    y.y = x.y * c1 + x.x * s1;
    *(float2*)(arr + (size_t)m * Cv + col) = y;
}

// ---------------------------------------------------------------------------
// Warp-local flash attention.
// Block = (b,h,t, 64-q-tile), 128 threads = 4 warps; each warp owns 16 q rows
// and ALL keys. Q fragments pinned in registers. Softmax fully warp-local.
// P permuted S->A via shfl (no smem staging).
// Qs/Ks: [d][col] stride 68 (LDS bank = 4*tig+gid, conflict-free).
// Vs:    [key][d] stride 68.
// ---------------------------------------------------------------------------
#define AQS 0
#define AKS (64 * 68)
#define AVS (2 * 64 * 68)
#define ATTN_SMEM_BYTES (3 * 64 * 68 * 4)   // 52224

__global__ __launch_bounds__(128) void attn_warp()
{
    extern __shared__ unsigned usm[];
    unsigned* Qs = usm + AQS;
    unsigned* Ks = usm + AKS;
    unsigned* Vs = usm + AVS;

    const int bx = blockIdx.x;
    const int nb = bx % 9;
    const int tt = (bx / 9) % Tv;
    const int hh = (bx / (9 * Tv)) % Hv;
    const int b  = bx / (9 * Tv * Hv);
    const int tprev = (tt == 0) ? 1 : tt - 1;
    const int tnext = (tt == Tv - 1) ? Tv - 2 : tt + 1;

    const int t = threadIdx.x;
    const int lane = t & 31;
    const int w = t >> 5;
    const int gid = lane >> 2, tig = lane & 3;
    const int wq = w * 16;              // warp's q-row base (0,16,32,48)

    const int lrow = t >> 1;            // loader row 0..63
    const int ldc  = (t & 1) * 32;      // loader d-half

    // ---- load Q tile (scaled by 1/8, tf32) into Qs[d][q] ----
    {
        const float* qb = g_q +
            (size_t)(b * TNv + tt * Nv + nb * 64 + lrow) * Cv + hh * HDv + ldc;
#pragma unroll
        for (int i = 0; i < 8; i++) {
            float4 v = *(const float4*)(qb + 4 * i);
            int d0 = ldc + 4 * i;
            Qs[(d0 + 0) * 68 + lrow] = tf32r(v.x * 0.125f);
            Qs[(d0 + 1) * 68 + lrow] = tf32r(v.y * 0.125f);
            Qs[(d0 + 2) * 68 + lrow] = tf32r(v.z * 0.125f);
            Qs[(d0 + 3) * 68 + lrow] = tf32r(v.w * 0.125f);
        }
    }
    __syncthreads();

    // ---- pin Q fragments in registers (8 k-chunks x 4 regs) ----
    unsigned qa[8][4];
#pragma unroll
    for (int kk = 0; kk < 8; kk++) {
        const int kr0 = (kk * 8 + tig) * 68;
        const int kr1 = (kk * 8 + tig + 4) * 68;
        qa[kk][0] = Qs[kr0 + wq + gid];
        qa[kk][1] = Qs[kr0 + wq + gid + 8];
        qa[kk][2] = Qs[kr1 + wq + gid];
        qa[kk][3] = Qs[kr1 + wq + gid + 8];
    }

    float m1 = -1e30f, m2 = -1e30f, l1 = 0.0f, l2 = 0.0f;
    float o[8][4];
#pragma unroll
    for (int j = 0; j < 8; j++)
#pragma unroll
        for (int r = 0; r < 4; r++) o[j][r] = 0.0f;

    const int src1 = gid * 4 + (tig >> 1);
    const int src2 = src1 + 2;
    const bool hi = (tig & 1) != 0;

    for (int kt = 0; kt < 18; kt++) {
        const int tsrc = (kt < 9) ? tprev : tnext;
        const int nk0 = (kt % 9) * 64;
        const size_t tok = (size_t)(b * TNv + tsrc * Nv + nk0 + lrow);
        const float* kb_ = g_k + tok * Cv + hh * HDv + ldc;
        const float* vb_ = g_v + tok * Cv + hh * HDv + ldc;

        __syncthreads();   // prior tile's reads of Ks/Vs complete
#pragma unroll
        for (int i = 0; i < 8; i++) {
            float4 kv = *(const float4*)(kb_ + 4 * i);
            float4 vv = *(const float4*)(vb_ + 4 * i);
            int d0 = ldc + 4 * i;
            Ks[(d0 + 0) * 68 + lrow] = tf32r(kv.x);
            Ks[(d0 + 1) * 68 + lrow] = tf32r(kv.y);
            Ks[(d0 + 2) * 68 + lrow] = tf32r(kv.z);
            Ks[(d0 + 3) * 68 + lrow] = tf32r(kv.w);
            uint4 pv;
            pv.x = tf32r(vv.x); pv.y = tf32r(vv.y);
            pv.z = tf32r(vv.z); pv.w = tf32r(vv.w);
            *(uint4*)&Vs[lrow * 68 + d0] = pv;
        }
        __syncthreads();

        // ---- S = Q @ K^T : 16 rows x 64 keys per warp ----
        float s[8][4];
#pragma unroll
        for (int j = 0; j < 8; j++)
#pragma unroll
            for (int r = 0; r < 4; r++) s[j][r] = 0.0f;
#pragma unroll
        for (int kk = 0; kk < 8; kk++) {
            const int kr0 = (kk * 8 + tig) * 68;
            const int kr1 = (kk * 8 + tig + 4) * 68;
#pragma unroll
            for (int j = 0; j < 8; j++) {
                unsigned bfr[2] = {Ks[kr0 + j * 8 + gid],
                                   Ks[kr1 + j * 8 + gid]};
                mma8(s[j], qa[kk], bfr);
            }
        }

        // ---- warp-local online softmax (rows gid and gid+8) ----
        float mx1 = -1e30f, mx2 = -1e30f;
#pragma unroll
        for (int j = 0; j < 8; j++) {
            mx1 = fmaxf(mx1, fmaxf(s[j][0], s[j][1]));
            mx2 = fmaxf(mx2, fmaxf(s[j][2], s[j][3]));
        }
        mx1 = fmaxf(mx1, __shfl_xor_sync(0xffffffffu, mx1, 1));
        mx1 = fmaxf(mx1, __shfl_xor_sync(0xffffffffu, mx1, 2));
        mx2 = fmaxf(mx2, __shfl_xor_sync(0xffffffffu, mx2, 1));
        mx2 = fmaxf(mx2, __shfl_xor_sync(0xffffffffu, mx2, 2));

        const float mn1 = fmaxf(m1, mx1);
        const float mn2 = fmaxf(m2, mx2);
        const float al1 = __expf(m1 - mn1);
        const float al2 = __expf(m2 - mn2);
        m1 = mn1; m2 = mn2;

        float rs1 = 0.0f, rs2 = 0.0f;
#pragma unroll
        for (int j = 0; j < 8; j++) {
            s[j][0] = __expf(s[j][0] - m1);
            s[j][1] = __expf(s[j][1] - m1);
            s[j][2] = __expf(s[j][2] - m2);
            s[j][3] = __expf(s[j][3] - m2);
            rs1 += s[j][0] + s[j][1];
            rs2 += s[j][2] + s[j][3];
        }
        rs1 += __shfl_xor_sync(0xffffffffu, rs1, 1);
        rs1 += __shfl_xor_sync(0xffffffffu, rs1, 2);
        rs2 += __shfl_xor_sync(0xffffffffu, rs2, 1);
        rs2 += __shfl_xor_sync(0xffffffffu, rs2, 2);
        l1 = l1 * al1 + rs1;
        l2 = l2 * al2 + rs2;

#pragma unroll
        for (int j = 0; j < 8; j++) {
            o[j][0] *= al1; o[j][1] *= al1;
            o[j][2] *= al2; o[j][3] *= al2;
        }

        // ---- O += P @ V : P permuted C-layout -> A-fragments via shfl ----
#pragma unroll
        for (int kk = 0; kk < 8; kk++) {
            unsigned p0 = tf32r(s[kk][0]);
            unsigned p1 = tf32r(s[kk][1]);
            unsigned p2 = tf32r(s[kk][2]);
            unsigned p3 = tf32r(s[kk][3]);
            unsigned u0 = __shfl_sync(0xffffffffu, p0, src1);
            unsigned u1 = __shfl_sync(0xffffffffu, p1, src1);
            unsigned u2 = __shfl_sync(0xffffffffu, p2, src1);
            unsigned u3 = __shfl_sync(0xffffffffu, p3, src1);
            unsigned w0 = __shfl_sync(0xffffffffu, p0, src2);
            unsigned w1 = __shfl_sync(0xffffffffu, p1, src2);
            unsigned w2 = __shfl_sync(0xffffffffu, p2, src2);
            unsigned w3 = __shfl_sync(0xffffffffu, p3, src2);
            unsigned a[4];
            a[0] = hi ? u1 : u0;
            a[1] = hi ? u3 : u2;
            a[2] = hi ? w1 : w0;
            a[3] = hi ? w3 : w2;
            const int kr0 = (kk * 8 + tig) * 68;
            const int kr1 = (kk * 8 + tig + 4) * 68;
#pragma unroll
            for (int j = 0; j < 8; j++) {
                unsigned bfr[2] = {Vs[kr0 + j * 8 + gid],
                                   Vs[kr1 + j * 8 + gid]};
                mma8(o[j], a, bfr);
            }
        }
    }

    // ---- normalize + write ----
    const float inv1 = 1.0f / l1;
    const float inv2 = 1.0f / l2;
    const size_t tok1 = (size_t)(b * TNv + tt * Nv + nb * 64 + wq + gid);
    float* ob1 = g_o + tok1 * Cv + hh * HDv;
    float* ob2 = g_o + (tok1 + 8) * Cv + hh * HDv;
#pragma unroll
    for (int j = 0; j < 8; j++) {
        float2 v1, v2;
        v1.x = o[j][0] * inv1; v1.y = o[j][1] * inv1;
        v2.x = o[j][2] * inv2; v2.y = o[j][3] * inv2;
        *(float2*)(ob1 + j * 8 + tig * 2) = v1;
        *(float2*)(ob2 + j * 8 + tig * 2) = v2;
    }
}

// ---------------------------------------------------------------------------
// Launch
// ---------------------------------------------------------------------------
extern "C" void kernel_launch(void* const* d_in, const int* in_sizes, int n_in,
                              void* d_out, int out_size)
{
    (void)in_sizes; (void)n_in; (void)out_size;
    const float* img  = (const float*)d_in[0];
    const float* fcos = (const float*)d_in[1];
    const float* fsin = (const float*)d_in[2];
    const float* Wq   = (const float*)d_in[3];
    const float* Wk   = (const float*)d_in[4];
    const float* Wv   = (const float*)d_in[5];
    const float* Wo   = (const float*)d_in[6];
    const float* bo   = (const float*)d_in[7];
    float* out = (float*)d_out;

    float *q, *k, *v, *o;
    cudaGetSymbolAddress((void**)&q, g_q);
    cudaGetSymbolAddress((void**)&k, g_k);
    cudaGetSymbolAddress((void**)&v, g_v);
    cudaGetSymbolAddress((void**)&o, g_o);

    cudaFuncSetAttribute(attn_warp,
                         cudaFuncAttributeMaxDynamicSharedMemorySize,
                         ATTN_SMEM_BYTES);

    dim3 gblk(256);
    dim3 ggrid(Cv / 128, Mrows / 128);   // (8, 72)

    gemm_tf32<<<ggrid, gblk>>>(img, Wq, q, nullptr);
    gemm_tf32<<<ggrid, gblk>>>(img, Wk, k, nullptr);
    gemm_tf32<<<ggrid, gblk>>>(img, Wv, v, nullptr);

    long pairs2 = 2L * Mrows * 512;
    int rblocks = (int)((pairs2 + 255) / 256);
    rope_kernel<<<rblocks, 256>>>(fcos, fsin);

    attn_warp<<<Bv * Hv * Tv * 9, 128, ATTN_SMEM_BYTES>>>();

    gemm_tf32<<<ggrid, gblk>>>(o, Wo, out, bo);
}

// round 7
// speedup vs baseline: 1.4962x; 1.4962x over previous
#include <cuda_runtime.h>
#include <cuda_fp16.h>
#include <math.h>
#include <stdint.h>

// Problem constants
#define Bv 2
#define Tv 8
#define Nv 576
#define Cv 1024
#define Hv 16
#define HDv 64
#define TNv (Tv * Nv)       // 4608
#define Mrows (Bv * TNv)    // 9216

// Scratch (device globals — no runtime allocation allowed)
__device__ float g_q[(size_t)Mrows * Cv];
__device__ float g_k[(size_t)Mrows * Cv];
__device__ float g_v[(size_t)Mrows * Cv];
__device__ float g_o[(size_t)Mrows * Cv];

// ---------------------------------------------------------------------------
// fp16 helpers
// ---------------------------------------------------------------------------
__device__ __forceinline__ unsigned f2h2(float lo, float hi) {
    __half2 h = __floats2half2_rn(lo, hi);
    return *(unsigned*)&h;
}

// m16n8k16 fp16 mma, fp32 accumulate
__device__ __forceinline__ void mma16(float d[4], const unsigned a[4],
                                      const unsigned b[2]) {
    asm volatile(
        "mma.sync.aligned.m16n8k16.row.col.f32.f16.f16.f32 "
        "{%0,%1,%2,%3},{%4,%5,%6,%7},{%8,%9},{%0,%1,%2,%3};"
        : "+f"(d[0]), "+f"(d[1]), "+f"(d[2]), "+f"(d[3])
        : "r"(a[0]), "r"(a[1]), "r"(a[2]), "r"(a[3]), "r"(b[0]), "r"(b[1]));
}

// ---------------------------------------------------------------------------
// NT GEMM via fp16 mma: C[m,n] = sum_k A[m,k] * W[n,k] (+ bias[n])
// Round-3 structure, half2 payload. Block 128x128, BK=32 (16 kp-rows),
// 8 warps (2m x 4n), warp tile 64x32.
// smem [kp][col] stride 136 uints, swizzle col ^ (((kp>>2)&3)<<3)
// (identical addresses to the proven tf32 version).
// ---------------------------------------------------------------------------
__global__ __launch_bounds__(256) void gemm_fp16(
    const float* __restrict__ A, const float* __restrict__ W,
    float* __restrict__ Cout, const float* __restrict__ bias)
{
    __shared__ unsigned As[16 * 136];
    __shared__ unsigned Bs[16 * 136];

    const int t = threadIdx.x;
    const int lane = t & 31;
    const int w = t >> 5;
    const int gid = lane >> 2, tig = lane & 3;
    const int wm = (w >> 2) * 64, wn = (w & 3) * 32;
    const int m0 = blockIdx.y * 128, n0 = blockIdx.x * 128;

    const int row0 = t >> 2;          // 0..63 (col within tile)
    const int kq = (t & 3) * 4;       // kp-row base: 0,4,8,12
    const int cstS = (t & 3) << 3;    // ((kp>>2)&3)<<3 for kp = kq+jj
    const int kf = (t & 3) * 8;       // float k offset = 2*kq

    const float* Ap0 = A + (size_t)(m0 + row0) * Cv + kf;
    const float* Ap1 = A + (size_t)(m0 + 64 + row0) * Cv + kf;
    const float* Wp0 = W + (size_t)(n0 + row0) * Cv + kf;
    const float* Wp1 = W + (size_t)(n0 + 64 + row0) * Cv + kf;

    float acc[4][4][4];
#pragma unroll
    for (int mt = 0; mt < 4; mt++)
#pragma unroll
        for (int nt = 0; nt < 4; nt++)
#pragma unroll
            for (int r = 0; r < 4; r++) acc[mt][nt][r] = 0.0f;

    // prefetch chunk 0 (8 floats per row -> 4 half2 per row)
    unsigned ua0[4], ua1[4], ub0[4], ub1[4];
    {
        float4 x0 = *(const float4*)Ap0, x1 = *(const float4*)(Ap0 + 4);
        float4 y0 = *(const float4*)Ap1, y1 = *(const float4*)(Ap1 + 4);
        float4 z0 = *(const float4*)Wp0, z1 = *(const float4*)(Wp0 + 4);
        float4 u0 = *(const float4*)Wp1, u1 = *(const float4*)(Wp1 + 4);
        ua0[0] = f2h2(x0.x, x0.y); ua0[1] = f2h2(x0.z, x0.w);
        ua0[2] = f2h2(x1.x, x1.y); ua0[3] = f2h2(x1.z, x1.w);
        ua1[0] = f2h2(y0.x, y0.y); ua1[1] = f2h2(y0.z, y0.w);
        ua1[2] = f2h2(y1.x, y1.y); ua1[3] = f2h2(y1.z, y1.w);
        ub0[0] = f2h2(z0.x, z0.y); ub0[1] = f2h2(z0.z, z0.w);
        ub0[2] = f2h2(z1.x, z1.y); ub0[3] = f2h2(z1.z, z1.w);
        ub1[0] = f2h2(u0.x, u0.y); ub1[1] = f2h2(u0.z, u0.w);
        ub1[2] = f2h2(u1.x, u1.y); ub1[3] = f2h2(u1.z, u1.w);
    }

    for (int ch = 0; ch < 32; ch++) {
        __syncthreads();
#pragma unroll
        for (int jj = 0; jj < 4; jj++) {
            int kr = (kq + jj) * 136;
            As[kr + (row0 ^ cstS)]        = ua0[jj];
            As[kr + ((row0 + 64) ^ cstS)] = ua1[jj];
            Bs[kr + (row0 ^ cstS)]        = ub0[jj];
            Bs[kr + ((row0 + 64) ^ cstS)] = ub1[jj];
        }
        __syncthreads();
        if (ch + 1 < 32) {
            const int kc = (ch + 1) * 32;
            float4 x0 = *(const float4*)(Ap0 + kc), x1 = *(const float4*)(Ap0 + kc + 4);
            float4 y0 = *(const float4*)(Ap1 + kc), y1 = *(const float4*)(Ap1 + kc + 4);
            float4 z0 = *(const float4*)(Wp0 + kc), z1 = *(const float4*)(Wp0 + kc + 4);
            float4 u0 = *(const float4*)(Wp1 + kc), u1 = *(const float4*)(Wp1 + kc + 4);
            ua0[0] = f2h2(x0.x, x0.y); ua0[1] = f2h2(x0.z, x0.w);
            ua0[2] = f2h2(x1.x, x1.y); ua0[3] = f2h2(x1.z, x1.w);
            ua1[0] = f2h2(y0.x, y0.y); ua1[1] = f2h2(y0.z, y0.w);
            ua1[2] = f2h2(y1.x, y1.y); ua1[3] = f2h2(y1.z, y1.w);
            ub0[0] = f2h2(z0.x, z0.y); ub0[1] = f2h2(z0.z, z0.w);
            ub0[2] = f2h2(z1.x, z1.y); ub0[3] = f2h2(z1.z, z1.w);
            ub1[0] = f2h2(u0.x, u0.y); ub1[1] = f2h2(u0.z, u0.w);
            ub1[2] = f2h2(u1.x, u1.y); ub1[3] = f2h2(u1.z, u1.w);
        }
        // two m16n8k16 steps: kp bases 0 and 8
#pragma unroll
        for (int s = 0; s < 2; s++) {
            const int kbp = s * 8;
            const int c0 = (((kbp + tig) >> 2) & 3) << 3;
            const int c1 = (((kbp + tig + 4) >> 2) & 3) << 3;
            const int kr0 = (kbp + tig) * 136;
            const int kr1 = (kbp + tig + 4) * 136;
            unsigned a[4][4], bb[4][2];
#pragma unroll
            for (int mt = 0; mt < 4; mt++) {
                int m = wm + mt * 16 + gid;
                a[mt][0] = As[kr0 + (m ^ c0)];
                a[mt][1] = As[kr0 + ((m + 8) ^ c0)];
                a[mt][2] = As[kr1 + (m ^ c1)];
                a[mt][3] = As[kr1 + ((m + 8) ^ c1)];
            }
#pragma unroll
            for (int nt = 0; nt < 4; nt++) {
                int n = wn + nt * 8 + gid;
                bb[nt][0] = Bs[kr0 + (n ^ c0)];
                bb[nt][1] = Bs[kr1 + (n ^ c1)];
            }
#pragma unroll
            for (int mt = 0; mt < 4; mt++)
#pragma unroll
                for (int nt = 0; nt < 4; nt++)
                    mma16(acc[mt][nt], a[mt], bb[nt]);
        }
    }

#pragma unroll
    for (int mt = 0; mt < 4; mt++) {
        int r = m0 + wm + mt * 16 + gid;
#pragma unroll
        for (int nt = 0; nt < 4; nt++) {
            int c = n0 + wn + nt * 8 + tig * 2;
            float b0v = bias ? bias[c] : 0.0f;
            float b1v = bias ? bias[c + 1] : 0.0f;
            float2 v0, v1;
            v0.x = acc[mt][nt][0] + b0v;
            v0.y = acc[mt][nt][1] + b1v;
            v1.x = acc[mt][nt][2] + b0v;
            v1.y = acc[mt][nt][3] + b1v;
            *(float2*)(Cout + (size_t)r * Cv + c) = v0;
            *(float2*)(Cout + (size_t)(r + 8) * Cv + c) = v1;
        }
    }
}

// ---------------------------------------------------------------------------
// RoPE (in-place on q and k, token-major [Mrows,1024] layout).
// ---------------------------------------------------------------------------
__global__ __launch_bounds__(256) void rope_kernel(
    const float* __restrict__ fcos, const float* __restrict__ fsin)
{
    const long total = (long)Mrows * 512;
    long gid = (long)blockIdx.x * blockDim.x + threadIdx.x;
    if (gid >= 2 * total) return;
    float* arr = (gid < total) ? g_q : g_k;
    long id = (gid < total) ? gid : (gid - total);

    int m = (int)(id / 512);
    int p = (int)(id % 512);
    int col = p * 2;
    int d = col & 63;
    int s = m % TNv;

    float c0 = fcos[(size_t)s * HDv + d];
    float c1 = fcos[(size_t)s * HDv + d + 1];
    float s0 = fsin[(size_t)s * HDv + d];
    float s1 = fsin[(size_t)s * HDv + d + 1];

    float2 x = *(float2*)(arr + (size_t)m * Cv + col);
    float2 y;
    y.x = x.x * c0 - x.y * s0;
    y.y = x.y * c1 + x.x * s1;
    *(float2*)(arr + (size_t)m * Cv + col) = y;
}

// ---------------------------------------------------------------------------
// Flash attention, fp16 mma (round-3 structure, half2 payload).
// Block = (b,h,t, 64-q-tile), 256 threads = 8 warps in 2(m) x 4(n) grid.
// Qs/Ks: [kp(32)][col] stride 72, kp = d/2, swizzle col ^ (((kp>>3)&3)<<3)
// Ps:    [keyp(32)][q] stride 72, keyp = key/2, same swizzle form
// Vs:    [keyp(32)][d] stride 72, half2 packs (key even, key odd), no swizzle
// ---------------------------------------------------------------------------
#define QS_OFF 0
#define KS_OFF 2304
#define VS_OFF 4608
#define PS_OFF 6912
#define RED_OFF 9216
#define MR_OFF 9472
#define LR_OFF 9536
#define AR_OFF 9600
#define ATTN_SMEM_WORDS 9664

__global__ __launch_bounds__(256) void attn_fp16()
{
    extern __shared__ unsigned usm[];
    unsigned* Qs = usm + QS_OFF;
    unsigned* Ks = usm + KS_OFF;
    unsigned* Vs = usm + VS_OFF;
    unsigned* Ps = usm + PS_OFF;
    float* red  = (float*)(usm + RED_OFF);   // [4][64]
    float* Mrow = (float*)(usm + MR_OFF);
    float* Lrow = (float*)(usm + LR_OFF);
    float* Arow = (float*)(usm + AR_OFF);

    const int bx = blockIdx.x;
    const int nb = bx % 9;
    const int tt = (bx / 9) % Tv;
    const int hh = (bx / (9 * Tv)) % Hv;
    const int b  = bx / (9 * Tv * Hv);
    const int tprev = (tt == 0) ? 1 : tt - 1;
    const int tnext = (tt == Tv - 1) ? Tv - 2 : tt + 1;

    const int t = threadIdx.x;
    const int lane = t & 31;
    const int w = t >> 5;
    const int gid = lane >> 2, tig = lane & 3;
    const int wm = w >> 2, wn = w & 3;

    // Q/K loader: token lrow, d range dc..dc+15 -> kp rows dc/2..dc/2+7
    const int lrow = t >> 2;
    const int dc = (t & 3) * 16;
    const int cstL = (t & 3) << 3;     // ((kp>>3)&3)<<3 for kp in [8(t&3),+8)

    // V loader: keyp vp = t>>3, d words 4(t&7) and 4(t&7)+32
    const int vp = t >> 3;
    const int vd = (t & 7) * 4;

    // ---- Q tile (scaled 1/8) ----
    {
        const float* qb =
            g_q + (size_t)(b * TNv + tt * Nv + nb * 64 + lrow) * Cv + hh * HDv + dc;
        const int kp0 = dc >> 1;
        const int cq = lrow ^ cstL;
#pragma unroll
        for (int j = 0; j < 4; j++) {
            float4 v = *(const float4*)(qb + 4 * j);
            Qs[(kp0 + 2 * j + 0) * 72 + cq] = f2h2(v.x * 0.125f, v.y * 0.125f);
            Qs[(kp0 + 2 * j + 1) * 72 + cq] = f2h2(v.z * 0.125f, v.w * 0.125f);
        }
    }
    if (t < 64) { Mrow[t] = -1e30f; Lrow[t] = 0.0f; }

    float o[2][2][4];
#pragma unroll
    for (int mi = 0; mi < 2; mi++)
#pragma unroll
        for (int nj = 0; nj < 2; nj++)
#pragma unroll
            for (int r = 0; r < 4; r++) o[mi][nj][r] = 0.0f;

    for (int kt = 0; kt < 18; kt++) {
        const int tsrc = (kt < 9) ? tprev : tnext;
        const int nk0 = (kt % 9) * 64;
        const size_t tokbase = (size_t)(b * TNv + tsrc * Nv + nk0);

        __syncthreads();   // prior tile's reads complete
        // K tile: same layout as Q
        {
            const float* kb_ =
                g_k + (tokbase + lrow) * Cv + hh * HDv + dc;
            const int kp0 = dc >> 1;
            const int ck = lrow ^ cstL;
#pragma unroll
            for (int j = 0; j < 4; j++) {
                float4 kv = *(const float4*)(kb_ + 4 * j);
                Ks[(kp0 + 2 * j + 0) * 72 + ck] = f2h2(kv.x, kv.y);
                Ks[(kp0 + 2 * j + 1) * 72 + ck] = f2h2(kv.z, kv.w);
            }
        }
        // V tile: pack key pairs (2vp, 2vp+1) across d
        {
            const float* va = g_v + (tokbase + 2 * vp) * Cv + hh * HDv;
            const float* vb = va + Cv;
            float4 a0 = *(const float4*)(va + vd);
            float4 b0 = *(const float4*)(vb + vd);
            float4 a1 = *(const float4*)(va + vd + 32);
            float4 b1 = *(const float4*)(vb + vd + 32);
            uint4 w0, w1;
            w0.x = f2h2(a0.x, b0.x); w0.y = f2h2(a0.y, b0.y);
            w0.z = f2h2(a0.z, b0.z); w0.w = f2h2(a0.w, b0.w);
            w1.x = f2h2(a1.x, b1.x); w1.y = f2h2(a1.y, b1.y);
            w1.z = f2h2(a1.z, b1.z); w1.w = f2h2(a1.w, b1.w);
            *(uint4*)&Vs[vp * 72 + vd] = w0;
            *(uint4*)&Vs[vp * 72 + vd + 32] = w1;
        }
        __syncthreads();

        // ---- S = Q @ K^T (4 k-steps of kp 8) ----
        float s[2][2][4];
#pragma unroll
        for (int mi = 0; mi < 2; mi++)
#pragma unroll
            for (int ni = 0; ni < 2; ni++)
#pragma unroll
                for (int r = 0; r < 4; r++) s[mi][ni][r] = 0.0f;
#pragma unroll
        for (int st = 0; st < 4; st++) {
            const int cs = (st & 3) << 3;
            const int kr0 = (st * 8 + tig) * 72;
            const int kr1 = (st * 8 + tig + 4) * 72;
            unsigned a[2][4], bb[2][2];
#pragma unroll
            for (int mi = 0; mi < 2; mi++) {
                int q0 = wm * 32 + mi * 16 + gid;
                a[mi][0] = Qs[kr0 + (q0 ^ cs)];
                a[mi][1] = Qs[kr0 + ((q0 + 8) ^ cs)];
                a[mi][2] = Qs[kr1 + (q0 ^ cs)];
                a[mi][3] = Qs[kr1 + ((q0 + 8) ^ cs)];
            }
#pragma unroll
            for (int ni = 0; ni < 2; ni++) {
                int kc = wn * 16 + ni * 8 + gid;
                bb[ni][0] = Ks[kr0 + (kc ^ cs)];
                bb[ni][1] = Ks[kr1 + (kc ^ cs)];
            }
#pragma unroll
            for (int mi = 0; mi < 2; mi++)
#pragma unroll
                for (int ni = 0; ni < 2; ni++)
                    mma16(s[mi][ni], a[mi], bb[ni]);
        }

        // ---- per-warp row max -> block reduce ----
#pragma unroll
        for (int mi = 0; mi < 2; mi++)
#pragma unroll
            for (int h2 = 0; h2 < 2; h2++) {
                float mx = fmaxf(fmaxf(s[mi][0][h2 * 2], s[mi][0][h2 * 2 + 1]),
                                 fmaxf(s[mi][1][h2 * 2], s[mi][1][h2 * 2 + 1]));
                mx = fmaxf(mx, __shfl_xor_sync(0xffffffffu, mx, 1));
                mx = fmaxf(mx, __shfl_xor_sync(0xffffffffu, mx, 2));
                if (tig == 0)
                    red[wn * 64 + wm * 32 + mi * 16 + h2 * 8 + gid] = mx;
            }
        __syncthreads();
        if (t < 64) {
            float tm = fmaxf(fmaxf(red[t], red[64 + t]),
                             fmaxf(red[128 + t], red[192 + t]));
            float mold = Mrow[t];
            float mnew = fmaxf(mold, tm);
            Mrow[t] = mnew;
            Arow[t] = __expf(mold - mnew);
        }
        __syncthreads();

        // ---- p = exp(s - m), stage P (half2 over key pairs), sums, rescale O
        const int cp = wn << 3;
        const int kp1 = wn * 8 + tig;        // keys wn*16+2tig, +1
        const int kp2 = kp1 + 4;             // keys wn*16+8+2tig, +1
#pragma unroll
        for (int mi = 0; mi < 2; mi++)
#pragma unroll
            for (int h2 = 0; h2 < 2; h2++) {
                int r = wm * 32 + mi * 16 + h2 * 8 + gid;
                float mrow = Mrow[r];
                float al = Arow[r];
                float p0 = __expf(s[mi][0][h2 * 2]     - mrow);
                float p1 = __expf(s[mi][0][h2 * 2 + 1] - mrow);
                float p2 = __expf(s[mi][1][h2 * 2]     - mrow);
                float p3 = __expf(s[mi][1][h2 * 2 + 1] - mrow);
                float rs = p0 + p1 + p2 + p3;
                rs += __shfl_xor_sync(0xffffffffu, rs, 1);
                rs += __shfl_xor_sync(0xffffffffu, rs, 2);
                if (tig == 0) red[wn * 64 + r] = rs;
                int rq = r ^ cp;
                Ps[kp1 * 72 + rq] = f2h2(p0, p1);
                Ps[kp2 * 72 + rq] = f2h2(p2, p3);
                o[mi][0][h2 * 2]     *= al;
                o[mi][0][h2 * 2 + 1] *= al;
                o[mi][1][h2 * 2]     *= al;
                o[mi][1][h2 * 2 + 1] *= al;
            }
        __syncthreads();
        if (t < 64)
            Lrow[t] = Lrow[t] * Arow[t] +
                      red[t] + red[64 + t] + red[128 + t] + red[192 + t];

        // ---- O += P @ V (4 k-steps over keyp) ----
#pragma unroll
        for (int st = 0; st < 4; st++) {
            const int cs = (st & 3) << 3;
            const int kr0 = (st * 8 + tig) * 72;
            const int kr1 = (st * 8 + tig + 4) * 72;
            unsigned a[2][4], bb[2][2];
#pragma unroll
            for (int mi = 0; mi < 2; mi++) {
                int q0 = wm * 32 + mi * 16 + gid;
                a[mi][0] = Ps[kr0 + (q0 ^ cs)];
                a[mi][1] = Ps[kr0 + ((q0 + 8) ^ cs)];
                a[mi][2] = Ps[kr1 + (q0 ^ cs)];
                a[mi][3] = Ps[kr1 + ((q0 + 8) ^ cs)];
            }
#pragma unroll
            for (int nj = 0; nj < 2; nj++) {
                int dcol = wn * 16 + nj * 8 + gid;
                bb[nj][0] = Vs[kr0 + dcol];
                bb[nj][1] = Vs[kr1 + dcol];
            }
#pragma unroll
            for (int mi = 0; mi < 2; mi++)
#pragma unroll
                for (int nj = 0; nj < 2; nj++)
                    mma16(o[mi][nj], a[mi], bb[nj]);
        }
    }

    __syncthreads();
#pragma unroll
    for (int mi = 0; mi < 2; mi++)
#pragma unroll
        for (int h2 = 0; h2 < 2; h2++) {
            int r = wm * 32 + mi * 16 + h2 * 8 + gid;
            float inv = 1.0f / Lrow[r];
            size_t token = (size_t)(b * TNv + tt * Nv + nb * 64 + r);
            float* ob = g_o + token * Cv + hh * HDv;
#pragma unroll
            for (int nj = 0; nj < 2; nj++) {
                int dcol = wn * 16 + nj * 8 + tig * 2;
                float2 v2;
                v2.x = o[mi][nj][h2 * 2] * inv;
                v2.y = o[mi][nj][h2 * 2 + 1] * inv;
                *(float2*)(ob + dcol) = v2;
            }
        }
}

// ---------------------------------------------------------------------------
// Launch
// ---------------------------------------------------------------------------
extern "C" void kernel_launch(void* const* d_in, const int* in_sizes, int n_in,
                              void* d_out, int out_size)
{
    (void)in_sizes; (void)n_in; (void)out_size;
    const float* img  = (const float*)d_in[0];
    const float* fcos = (const float*)d_in[1];
    const float* fsin = (const float*)d_in[2];
    const float* Wq   = (const float*)d_in[3];
    const float* Wk   = (const float*)d_in[4];
    const float* Wv   = (const float*)d_in[5];
    const float* Wo   = (const float*)d_in[6];
    const float* bo   = (const float*)d_in[7];
    float* out = (float*)d_out;

    float *q, *k, *v, *o;
    cudaGetSymbolAddress((void**)&q, g_q);
    cudaGetSymbolAddress((void**)&k, g_k);
    cudaGetSymbolAddress((void**)&v, g_v);
    cudaGetSymbolAddress((void**)&o, g_o);

    cudaFuncSetAttribute(attn_fp16,
                         cudaFuncAttributeMaxDynamicSharedMemorySize,
                         ATTN_SMEM_WORDS * (int)sizeof(unsigned));

    dim3 gblk(256);
    dim3 ggrid(Cv / 128, Mrows / 128);   // (8, 72)

    gemm_fp16<<<ggrid, gblk>>>(img, Wq, q, nullptr);
    gemm_fp16<<<ggrid, gblk>>>(img, Wk, k, nullptr);
    gemm_fp16<<<ggrid, gblk>>>(img, Wv, v, nullptr);

    long pairs2 = 2L * Mrows * 512;
    int rblocks = (int)((pairs2 + 255) / 256);
    rope_kernel<<<rblocks, 256>>>(fcos, fsin);

    attn_fp16<<<Bv * Hv * Tv * 9, 256,
                ATTN_SMEM_WORDS * sizeof(unsigned)>>>();

    gemm_fp16<<<ggrid, gblk>>>(o, Wo, out, bo);
}

// round 8
// speedup vs baseline: 1.7970x; 1.2011x over previous
#include <cuda_runtime.h>
#include <cuda_fp16.h>
#include <math.h>
#include <stdint.h>

// Problem constants
#define Bv 2
#define Tv 8
#define Nv 576
#define Cv 1024
#define Hv 16
#define HDv 64
#define TNv (Tv * Nv)       // 4608
#define Mrows (Bv * TNv)    // 9216
#define CW (Cv / 2)         // 512 uint words per token row

// Scratch (device globals — no runtime allocation allowed). Half precision.
__device__ __half g_qh[(size_t)Mrows * Cv];
__device__ __half g_kh[(size_t)Mrows * Cv];
__device__ __half g_vh[(size_t)Mrows * Cv];
__device__ __half g_oh[(size_t)Mrows * Cv];

// ---------------------------------------------------------------------------
// fp16 helpers
// ---------------------------------------------------------------------------
__device__ __forceinline__ unsigned f2h2(float lo, float hi) {
    __half2 h = __floats2half2_rn(lo, hi);
    return *(unsigned*)&h;
}

// (a.h0, b.h0) and (a.h1, b.h1) half2 lane combines via PRMT
__device__ __forceinline__ unsigned h2lows(unsigned a, unsigned b) {
    unsigned r;
    asm("prmt.b32 %0, %1, %2, 0x5410;" : "=r"(r) : "r"(a), "r"(b));
    return r;
}
__device__ __forceinline__ unsigned h2highs(unsigned a, unsigned b) {
    unsigned r;
    asm("prmt.b32 %0, %1, %2, 0x7632;" : "=r"(r) : "r"(a), "r"(b));
    return r;
}

// m16n8k16 fp16 mma, fp32 accumulate
__device__ __forceinline__ void mma16(float d[4], const unsigned a[4],
                                      const unsigned b[2]) {
    asm volatile(
        "mma.sync.aligned.m16n8k16.row.col.f32.f16.f16.f32 "
        "{%0,%1,%2,%3},{%4,%5,%6,%7},{%8,%9},{%0,%1,%2,%3};"
        : "+f"(d[0]), "+f"(d[1]), "+f"(d[2]), "+f"(d[3])
        : "r"(a[0]), "r"(a[1]), "r"(a[2]), "r"(a[3]), "r"(b[0]), "r"(b[1]));
}

// ---------------------------------------------------------------------------
// Projection GEMM: out[m,n] = half( rope?( scale * sum_k A[m,k]*W[n,k] ) )
// A fp32 [Mrows,1024], W fp32 [1024,1024] NT, out __half.
// If fcos != nullptr: apply RoPE (pair (c, c+1), c even) in fp32 pre-round.
// Structure identical to proven round-7 gemm_fp16.
// ---------------------------------------------------------------------------
__global__ __launch_bounds__(256) void gemm_proj(
    const float* __restrict__ A, const float* __restrict__ W,
    __half* __restrict__ Out,
    const float* __restrict__ fcos, const float* __restrict__ fsin,
    float scale)
{
    __shared__ unsigned As[16 * 136];
    __shared__ unsigned Bs[16 * 136];

    const int t = threadIdx.x;
    const int lane = t & 31;
    const int w = t >> 5;
    const int gid = lane >> 2, tig = lane & 3;
    const int wm = (w >> 2) * 64, wn = (w & 3) * 32;
    const int m0 = blockIdx.y * 128, n0 = blockIdx.x * 128;

    const int row0 = t >> 2;
    const int kq = (t & 3) * 4;
    const int cstS = (t & 3) << 3;
    const int kf = (t & 3) * 8;

    const float* Ap0 = A + (size_t)(m0 + row0) * Cv + kf;
    const float* Ap1 = A + (size_t)(m0 + 64 + row0) * Cv + kf;
    const float* Wp0 = W + (size_t)(n0 + row0) * Cv + kf;
    const float* Wp1 = W + (size_t)(n0 + 64 + row0) * Cv + kf;

    float acc[4][4][4];
#pragma unroll
    for (int mt = 0; mt < 4; mt++)
#pragma unroll
        for (int nt = 0; nt < 4; nt++)
#pragma unroll
            for (int r = 0; r < 4; r++) acc[mt][nt][r] = 0.0f;

    unsigned ua0[4], ua1[4], ub0[4], ub1[4];
    {
        float4 x0 = *(const float4*)Ap0, x1 = *(const float4*)(Ap0 + 4);
        float4 y0 = *(const float4*)Ap1, y1 = *(const float4*)(Ap1 + 4);
        float4 z0 = *(const float4*)Wp0, z1 = *(const float4*)(Wp0 + 4);
        float4 u0 = *(const float4*)Wp1, u1 = *(const float4*)(Wp1 + 4);
        ua0[0] = f2h2(x0.x, x0.y); ua0[1] = f2h2(x0.z, x0.w);
        ua0[2] = f2h2(x1.x, x1.y); ua0[3] = f2h2(x1.z, x1.w);
        ua1[0] = f2h2(y0.x, y0.y); ua1[1] = f2h2(y0.z, y0.w);
        ua1[2] = f2h2(y1.x, y1.y); ua1[3] = f2h2(y1.z, y1.w);
        ub0[0] = f2h2(z0.x, z0.y); ub0[1] = f2h2(z0.z, z0.w);
        ub0[2] = f2h2(z1.x, z1.y); ub0[3] = f2h2(z1.z, z1.w);
        ub1[0] = f2h2(u0.x, u0.y); ub1[1] = f2h2(u0.z, u0.w);
        ub1[2] = f2h2(u1.x, u1.y); ub1[3] = f2h2(u1.z, u1.w);
    }

    for (int ch = 0; ch < 32; ch++) {
        __syncthreads();
#pragma unroll
        for (int jj = 0; jj < 4; jj++) {
            int kr = (kq + jj) * 136;
            As[kr + (row0 ^ cstS)]        = ua0[jj];
            As[kr + ((row0 + 64) ^ cstS)] = ua1[jj];
            Bs[kr + (row0 ^ cstS)]        = ub0[jj];
            Bs[kr + ((row0 + 64) ^ cstS)] = ub1[jj];
        }
        __syncthreads();
        if (ch + 1 < 32) {
            const int kc = (ch + 1) * 32;
            float4 x0 = *(const float4*)(Ap0 + kc), x1 = *(const float4*)(Ap0 + kc + 4);
            float4 y0 = *(const float4*)(Ap1 + kc), y1 = *(const float4*)(Ap1 + kc + 4);
            float4 z0 = *(const float4*)(Wp0 + kc), z1 = *(const float4*)(Wp0 + kc + 4);
            float4 u0 = *(const float4*)(Wp1 + kc), u1 = *(const float4*)(Wp1 + kc + 4);
            ua0[0] = f2h2(x0.x, x0.y); ua0[1] = f2h2(x0.z, x0.w);
            ua0[2] = f2h2(x1.x, x1.y); ua0[3] = f2h2(x1.z, x1.w);
            ua1[0] = f2h2(y0.x, y0.y); ua1[1] = f2h2(y0.z, y0.w);
            ua1[2] = f2h2(y1.x, y1.y); ua1[3] = f2h2(y1.z, y1.w);
            ub0[0] = f2h2(z0.x, z0.y); ub0[1] = f2h2(z0.z, z0.w);
            ub0[2] = f2h2(z1.x, z1.y); ub0[3] = f2h2(z1.z, z1.w);
            ub1[0] = f2h2(u0.x, u0.y); ub1[1] = f2h2(u0.z, u0.w);
            ub1[2] = f2h2(u1.x, u1.y); ub1[3] = f2h2(u1.z, u1.w);
        }
#pragma unroll
        for (int s = 0; s < 2; s++) {
            const int kbp = s * 8;
            const int c0 = (((kbp + tig) >> 2) & 3) << 3;
            const int c1 = (((kbp + tig + 4) >> 2) & 3) << 3;
            const int kr0 = (kbp + tig) * 136;
            const int kr1 = (kbp + tig + 4) * 136;
            unsigned a[4][4], bb[4][2];
#pragma unroll
            for (int mt = 0; mt < 4; mt++) {
                int m = wm + mt * 16 + gid;
                a[mt][0] = As[kr0 + (m ^ c0)];
                a[mt][1] = As[kr0 + ((m + 8) ^ c0)];
                a[mt][2] = As[kr1 + (m ^ c1)];
                a[mt][3] = As[kr1 + ((m + 8) ^ c1)];
            }
#pragma unroll
            for (int nt = 0; nt < 4; nt++) {
                int n = wn + nt * 8 + gid;
                bb[nt][0] = Bs[kr0 + (n ^ c0)];
                bb[nt][1] = Bs[kr1 + (n ^ c1)];
            }
#pragma unroll
            for (int mt = 0; mt < 4; mt++)
#pragma unroll
                for (int nt = 0; nt < 4; nt++)
                    mma16(acc[mt][nt], a[mt], bb[nt]);
        }
    }

    // Epilogue: optional fp32 RoPE + scale, round once to half.
    const bool rope = (fcos != nullptr);
#pragma unroll
    for (int mt = 0; mt < 4; mt++) {
        const int r = m0 + wm + mt * 16 + gid;
        const int r8 = r + 8;
        const int s_lo = (r  >= TNv) ? r  - TNv : r;
        const int s_hi = (r8 >= TNv) ? r8 - TNv : r8;
#pragma unroll
        for (int nt = 0; nt < 4; nt++) {
            const int c = n0 + wn + nt * 8 + tig * 2;   // even
            float a0 = acc[mt][nt][0] * scale;
            float a1 = acc[mt][nt][1] * scale;
            float a2 = acc[mt][nt][2] * scale;
            float a3 = acc[mt][nt][3] * scale;
            if (rope) {
                const int d = c & 63;
                float2 cl = *(const float2*)(fcos + (size_t)s_lo * HDv + d);
                float2 sl = *(const float2*)(fsin + (size_t)s_lo * HDv + d);
                float2 chh = *(const float2*)(fcos + (size_t)s_hi * HDv + d);
                float2 sh = *(const float2*)(fsin + (size_t)s_hi * HDv + d);
                float y0 = a0 * cl.x - a1 * sl.x;
                float y1 = a1 * cl.y + a0 * sl.y;
                float y2 = a2 * chh.x - a3 * sh.x;
                float y3 = a3 * chh.y + a2 * sh.y;
                a0 = y0; a1 = y1; a2 = y2; a3 = y3;
            }
            *(unsigned*)(Out + (size_t)r  * Cv + c) = f2h2(a0, a1);
            *(unsigned*)(Out + (size_t)r8 * Cv + c) = f2h2(a2, a3);
        }
    }
}

// ---------------------------------------------------------------------------
// Output GEMM: out[m,n] = sum_k Ah[m,k]*W[n,k] + bias[n]; Ah is __half.
// ---------------------------------------------------------------------------
__global__ __launch_bounds__(256) void gemm_out(
    const __half* __restrict__ Ah, const float* __restrict__ W,
    float* __restrict__ Cout, const float* __restrict__ bias)
{
    __shared__ unsigned As[16 * 136];
    __shared__ unsigned Bs[16 * 136];

    const int t = threadIdx.x;
    const int lane = t & 31;
    const int w = t >> 5;
    const int gid = lane >> 2, tig = lane & 3;
    const int wm = (w >> 2) * 64, wn = (w & 3) * 32;
    const int m0 = blockIdx.y * 128, n0 = blockIdx.x * 128;

    const int row0 = t >> 2;
    const int kq = (t & 3) * 4;
    const int cstS = (t & 3) << 3;
    const int kf = (t & 3) * 8;        // channel offset
    const int kw = (t & 3) * 4;        // word offset

    const unsigned* Ap0 = (const unsigned*)Ah + (size_t)(m0 + row0) * CW + kw;
    const unsigned* Ap1 = (const unsigned*)Ah + (size_t)(m0 + 64 + row0) * CW + kw;
    const float* Wp0 = W + (size_t)(n0 + row0) * Cv + kf;
    const float* Wp1 = W + (size_t)(n0 + 64 + row0) * Cv + kf;

    float acc[4][4][4];
#pragma unroll
    for (int mt = 0; mt < 4; mt++)
#pragma unroll
        for (int nt = 0; nt < 4; nt++)
#pragma unroll
            for (int r = 0; r < 4; r++) acc[mt][nt][r] = 0.0f;

    unsigned ua0[4], ua1[4], ub0[4], ub1[4];
    {
        uint4 xa = *(const uint4*)Ap0;
        uint4 ya = *(const uint4*)Ap1;
        ua0[0] = xa.x; ua0[1] = xa.y; ua0[2] = xa.z; ua0[3] = xa.w;
        ua1[0] = ya.x; ua1[1] = ya.y; ua1[2] = ya.z; ua1[3] = ya.w;
        float4 z0 = *(const float4*)Wp0, z1 = *(const float4*)(Wp0 + 4);
        float4 u0 = *(const float4*)Wp1, u1 = *(const float4*)(Wp1 + 4);
        ub0[0] = f2h2(z0.x, z0.y); ub0[1] = f2h2(z0.z, z0.w);
        ub0[2] = f2h2(z1.x, z1.y); ub0[3] = f2h2(z1.z, z1.w);
        ub1[0] = f2h2(u0.x, u0.y); ub1[1] = f2h2(u0.z, u0.w);
        ub1[2] = f2h2(u1.x, u1.y); ub1[3] = f2h2(u1.z, u1.w);
    }

    for (int ch = 0; ch < 32; ch++) {
        __syncthreads();
#pragma unroll
        for (int jj = 0; jj < 4; jj++) {
            int kr = (kq + jj) * 136;
            As[kr + (row0 ^ cstS)]        = ua0[jj];
            As[kr + ((row0 + 64) ^ cstS)] = ua1[jj];
            Bs[kr + (row0 ^ cstS)]        = ub0[jj];
            Bs[kr + ((row0 + 64) ^ cstS)] = ub1[jj];
        }
        __syncthreads();
        if (ch + 1 < 32) {
            const int kc = (ch + 1) * 32;
            uint4 xa = *(const uint4*)(Ap0 + (ch + 1) * 16);
            uint4 ya = *(const uint4*)(Ap1 + (ch + 1) * 16);
            ua0[0] = xa.x; ua0[1] = xa.y; ua0[2] = xa.z; ua0[3] = xa.w;
            ua1[0] = ya.x; ua1[1] = ya.y; ua1[2] = ya.z; ua1[3] = ya.w;
            float4 z0 = *(const float4*)(Wp0 + kc), z1 = *(const float4*)(Wp0 + kc + 4);
            float4 u0 = *(const float4*)(Wp1 + kc), u1 = *(const float4*)(Wp1 + kc + 4);
            ub0[0] = f2h2(z0.x, z0.y); ub0[1] = f2h2(z0.z, z0.w);
            ub0[2] = f2h2(z1.x, z1.y); ub0[3] = f2h2(z1.z, z1.w);
            ub1[0] = f2h2(u0.x, u0.y); ub1[1] = f2h2(u0.z, u0.w);
            ub1[2] = f2h2(u1.x, u1.y); ub1[3] = f2h2(u1.z, u1.w);
        }
#pragma unroll
        for (int s = 0; s < 2; s++) {
            const int kbp = s * 8;
            const int c0 = (((kbp + tig) >> 2) & 3) << 3;
            const int c1 = (((kbp + tig + 4) >> 2) & 3) << 3;
            const int kr0 = (kbp + tig) * 136;
            const int kr1 = (kbp + tig + 4) * 136;
            unsigned a[4][4], bb[4][2];
#pragma unroll
            for (int mt = 0; mt < 4; mt++) {
                int m = wm + mt * 16 + gid;
                a[mt][0] = As[kr0 + (m ^ c0)];
                a[mt][1] = As[kr0 + ((m + 8) ^ c0)];
                a[mt][2] = As[kr1 + (m ^ c1)];
                a[mt][3] = As[kr1 + ((m + 8) ^ c1)];
            }
#pragma unroll
            for (int nt = 0; nt < 4; nt++) {
                int n = wn + nt * 8 + gid;
                bb[nt][0] = Bs[kr0 + (n ^ c0)];
                bb[nt][1] = Bs[kr1 + (n ^ c1)];
            }
#pragma unroll
            for (int mt = 0; mt < 4; mt++)
#pragma unroll
                for (int nt = 0; nt < 4; nt++)
                    mma16(acc[mt][nt], a[mt], bb[nt]);
        }
    }

#pragma unroll
    for (int mt = 0; mt < 4; mt++) {
        int r = m0 + wm + mt * 16 + gid;
#pragma unroll
        for (int nt = 0; nt < 4; nt++) {
            int c = n0 + wn + nt * 8 + tig * 2;
            float b0v = bias[c], b1v = bias[c + 1];
            float2 v0, v1;
            v0.x = acc[mt][nt][0] + b0v;
            v0.y = acc[mt][nt][1] + b1v;
            v1.x = acc[mt][nt][2] + b0v;
            v1.y = acc[mt][nt][3] + b1v;
            *(float2*)(Cout + (size_t)r * Cv + c) = v0;
            *(float2*)(Cout + (size_t)(r + 8) * Cv + c) = v1;
        }
    }
}

// ---------------------------------------------------------------------------
// Flash attention, fp16 (round-7 core; loaders read half directly).
// Qs/Ks: [kp(32)][col] stride 72 (kp = d/2);  Ps: [keyp(32)][q] stride 72
// Vs:    [keyp(32)][d] stride 72 (half2 = (key even, key odd))
// ---------------------------------------------------------------------------
#define QS_OFF 0
#define KS_OFF 2304
#define VS_OFF 4608
#define PS_OFF 6912
#define RED_OFF 9216
#define MR_OFF 9472
#define LR_OFF 9536
#define AR_OFF 9600
#define ATTN_SMEM_WORDS 9664

__global__ __launch_bounds__(256) void attn_fp16()
{
    extern __shared__ unsigned usm[];
    unsigned* Qs = usm + QS_OFF;
    unsigned* Ks = usm + KS_OFF;
    unsigned* Vs = usm + VS_OFF;
    unsigned* Ps = usm + PS_OFF;
    float* red  = (float*)(usm + RED_OFF);
    float* Mrow = (float*)(usm + MR_OFF);
    float* Lrow = (float*)(usm + LR_OFF);
    float* Arow = (float*)(usm + AR_OFF);

    const int bx = blockIdx.x;
    const int nb = bx % 9;
    const int tt = (bx / 9) % Tv;
    const int hh = (bx / (9 * Tv)) % Hv;
    const int b  = bx / (9 * Tv * Hv);
    const int tprev = (tt == 0) ? 1 : tt - 1;
    const int tnext = (tt == Tv - 1) ? Tv - 2 : tt + 1;

    const int t = threadIdx.x;
    const int lane = t & 31;
    const int w = t >> 5;
    const int gid = lane >> 2, tig = lane & 3;
    const int wm = w >> 2, wn = w & 3;

    const int lrow = t >> 2;           // Q/K loader token
    const int dc = (t & 3) * 16;       // channel base
    const int cstL = (t & 3) << 3;

    const int vp = t >> 3;             // V loader keyp
    const int vd = (t & 7) * 4;        // V output word base

    // ---- Q tile: direct half2 copy (already roped + scaled) ----
    {
        const unsigned* qb = (const unsigned*)g_qh +
            (size_t)(b * TNv + tt * Nv + nb * 64 + lrow) * CW + hh * 32 + (dc >> 1);
        uint4 u0 = *(const uint4*)qb;
        uint4 u1 = *(const uint4*)(qb + 4);
        const int kp0 = dc >> 1;
        const int cq = lrow ^ cstL;
        Qs[(kp0 + 0) * 72 + cq] = u0.x;
        Qs[(kp0 + 1) * 72 + cq] = u0.y;
        Qs[(kp0 + 2) * 72 + cq] = u0.z;
        Qs[(kp0 + 3) * 72 + cq] = u0.w;
        Qs[(kp0 + 4) * 72 + cq] = u1.x;
        Qs[(kp0 + 5) * 72 + cq] = u1.y;
        Qs[(kp0 + 6) * 72 + cq] = u1.z;
        Qs[(kp0 + 7) * 72 + cq] = u1.w;
    }
    if (t < 64) { Mrow[t] = -1e30f; Lrow[t] = 0.0f; }

    float o[2][2][4];
#pragma unroll
    for (int mi = 0; mi < 2; mi++)
#pragma unroll
        for (int nj = 0; nj < 2; nj++)
#pragma unroll
            for (int r = 0; r < 4; r++) o[mi][nj][r] = 0.0f;

    for (int kt = 0; kt < 18; kt++) {
        const int tsrc = (kt < 9) ? tprev : tnext;
        const int nk0 = (kt % 9) * 64;
        const size_t tokbase = (size_t)(b * TNv + tsrc * Nv + nk0);

        __syncthreads();
        // K tile: direct half2 copy
        {
            const unsigned* kb_ = (const unsigned*)g_kh +
                (tokbase + lrow) * CW + hh * 32 + (dc >> 1);
            uint4 u0 = *(const uint4*)kb_;
            uint4 u1 = *(const uint4*)(kb_ + 4);
            const int kp0 = dc >> 1;
            const int ck = lrow ^ cstL;
            Ks[(kp0 + 0) * 72 + ck] = u0.x;
            Ks[(kp0 + 1) * 72 + ck] = u0.y;
            Ks[(kp0 + 2) * 72 + ck] = u0.z;
            Ks[(kp0 + 3) * 72 + ck] = u0.w;
            Ks[(kp0 + 4) * 72 + ck] = u1.x;
            Ks[(kp0 + 5) * 72 + ck] = u1.y;
            Ks[(kp0 + 6) * 72 + ck] = u1.z;
            Ks[(kp0 + 7) * 72 + ck] = u1.w;
        }
        // V tile: transpose key pairs via PRMT
        {
            const unsigned* va = (const unsigned*)g_vh +
                (tokbase + 2 * vp) * CW + hh * 32 + (vd >> 1);
            const unsigned* vb2 = va + CW;
            uint2 A0 = *(const uint2*)va;
            uint2 B0 = *(const uint2*)vb2;
            uint2 A1 = *(const uint2*)(va + 16);
            uint2 B1 = *(const uint2*)(vb2 + 16);
            unsigned* vr = &Vs[vp * 72 + vd];
            vr[0] = h2lows(A0.x, B0.x);
            vr[1] = h2highs(A0.x, B0.x);
            vr[2] = h2lows(A0.y, B0.y);
            vr[3] = h2highs(A0.y, B0.y);
            vr[32] = h2lows(A1.x, B1.x);
            vr[33] = h2highs(A1.x, B1.x);
            vr[34] = h2lows(A1.y, B1.y);
            vr[35] = h2highs(A1.y, B1.y);
        }
        __syncthreads();

        // ---- S = Q @ K^T ----
        float s[2][2][4];
#pragma unroll
        for (int mi = 0; mi < 2; mi++)
#pragma unroll
            for (int ni = 0; ni < 2; ni++)
#pragma unroll
                for (int r = 0; r < 4; r++) s[mi][ni][r] = 0.0f;
#pragma unroll
        for (int st = 0; st < 4; st++) {
            const int cs = (st & 3) << 3;
            const int kr0 = (st * 8 + tig) * 72;
            const int kr1 = (st * 8 + tig + 4) * 72;
            unsigned a[2][4], bb[2][2];
#pragma unroll
            for (int mi = 0; mi < 2; mi++) {
                int q0 = wm * 32 + mi * 16 + gid;
                a[mi][0] = Qs[kr0 + (q0 ^ cs)];
                a[mi][1] = Qs[kr0 + ((q0 + 8) ^ cs)];
                a[mi][2] = Qs[kr1 + (q0 ^ cs)];
                a[mi][3] = Qs[kr1 + ((q0 + 8) ^ cs)];
            }
#pragma unroll
            for (int ni = 0; ni < 2; ni++) {
                int kc = wn * 16 + ni * 8 + gid;
                bb[ni][0] = Ks[kr0 + (kc ^ cs)];
                bb[ni][1] = Ks[kr1 + (kc ^ cs)];
            }
#pragma unroll
            for (int mi = 0; mi < 2; mi++)
#pragma unroll
                for (int ni = 0; ni < 2; ni++)
                    mma16(s[mi][ni], a[mi], bb[ni]);
        }

        // ---- row max -> block reduce ----
#pragma unroll
        for (int mi = 0; mi < 2; mi++)
#pragma unroll
            for (int h2 = 0; h2 < 2; h2++) {
                float mx = fmaxf(fmaxf(s[mi][0][h2 * 2], s[mi][0][h2 * 2 + 1]),
                                 fmaxf(s[mi][1][h2 * 2], s[mi][1][h2 * 2 + 1]));
                mx = fmaxf(mx, __shfl_xor_sync(0xffffffffu, mx, 1));
                mx = fmaxf(mx, __shfl_xor_sync(0xffffffffu, mx, 2));
                if (tig == 0)
                    red[wn * 64 + wm * 32 + mi * 16 + h2 * 8 + gid] = mx;
            }
        __syncthreads();
        if (t < 64) {
            float tm = fmaxf(fmaxf(red[t], red[64 + t]),
                             fmaxf(red[128 + t], red[192 + t]));
            float mold = Mrow[t];
            float mnew = fmaxf(mold, tm);
            Mrow[t] = mnew;
            Arow[t] = __expf(mold - mnew);
        }
        __syncthreads();

        // ---- p = exp(s-m), stage P, sums, rescale O ----
        const int cp = wn << 3;
        const int kp1 = wn * 8 + tig;
        const int kp2 = kp1 + 4;
#pragma unroll
        for (int mi = 0; mi < 2; mi++)
#pragma unroll
            for (int h2 = 0; h2 < 2; h2++) {
                int r = wm * 32 + mi * 16 + h2 * 8 + gid;
                float mrow = Mrow[r];
                float al = Arow[r];
                float p0 = __expf(s[mi][0][h2 * 2]     - mrow);
                float p1 = __expf(s[mi][0][h2 * 2 + 1] - mrow);
                float p2 = __expf(s[mi][1][h2 * 2]     - mrow);
                float p3 = __expf(s[mi][1][h2 * 2 + 1] - mrow);
                float rs = p0 + p1 + p2 + p3;
                rs += __shfl_xor_sync(0xffffffffu, rs, 1);
                rs += __shfl_xor_sync(0xffffffffu, rs, 2);
                if (tig == 0) red[wn * 64 + r] = rs;
                int rq = r ^ cp;
                Ps[kp1 * 72 + rq] = f2h2(p0, p1);
                Ps[kp2 * 72 + rq] = f2h2(p2, p3);
                o[mi][0][h2 * 2]     *= al;
                o[mi][0][h2 * 2 + 1] *= al;
                o[mi][1][h2 * 2]     *= al;
                o[mi][1][h2 * 2 + 1] *= al;
            }
        __syncthreads();
        if (t < 64)
            Lrow[t] = Lrow[t] * Arow[t] +
                      red[t] + red[64 + t] + red[128 + t] + red[192 + t];

        // ---- O += P @ V ----
#pragma unroll
        for (int st = 0; st < 4; st++) {
            const int cs = (st & 3) << 3;
            const int kr0 = (st * 8 + tig) * 72;
            const int kr1 = (st * 8 + tig + 4) * 72;
            unsigned a[2][4], bb[2][2];
#pragma unroll
            for (int mi = 0; mi < 2; mi++) {
                int q0 = wm * 32 + mi * 16 + gid;
                a[mi][0] = Ps[kr0 + (q0 ^ cs)];
                a[mi][1] = Ps[kr0 + ((q0 + 8) ^ cs)];
                a[mi][2] = Ps[kr1 + (q0 ^ cs)];
                a[mi][3] = Ps[kr1 + ((q0 + 8) ^ cs)];
            }
#pragma unroll
            for (int nj = 0; nj < 2; nj++) {
                int dcol = wn * 16 + nj * 8 + gid;
                bb[nj][0] = Vs[kr0 + dcol];
                bb[nj][1] = Vs[kr1 + dcol];
            }
#pragma unroll
            for (int mi = 0; mi < 2; mi++)
#pragma unroll
                for (int nj = 0; nj < 2; nj++)
                    mma16(o[mi][nj], a[mi], bb[nj]);
        }
    }

    __syncthreads();
#pragma unroll
    for (int mi = 0; mi < 2; mi++)
#pragma unroll
        for (int h2 = 0; h2 < 2; h2++) {
            int r = wm * 32 + mi * 16 + h2 * 8 + gid;
            float inv = 1.0f / Lrow[r];
            size_t token = (size_t)(b * TNv + tt * Nv + nb * 64 + r);
            __half* ob = g_oh + token * Cv + hh * HDv;
#pragma unroll
            for (int nj = 0; nj < 2; nj++) {
                int dcol = wn * 16 + nj * 8 + tig * 2;
                *(unsigned*)(ob + dcol) =
                    f2h2(o[mi][nj][h2 * 2] * inv, o[mi][nj][h2 * 2 + 1] * inv);
            }
        }
}

// ---------------------------------------------------------------------------
// Launch
// ---------------------------------------------------------------------------
extern "C" void kernel_launch(void* const* d_in, const int* in_sizes, int n_in,
                              void* d_out, int out_size)
{
    (void)in_sizes; (void)n_in; (void)out_size;
    const float* img  = (const float*)d_in[0];
    const float* fcos = (const float*)d_in[1];
    const float* fsin = (const float*)d_in[2];
    const float* Wq   = (const float*)d_in[3];
    const float* Wk   = (const float*)d_in[4];
    const float* Wv   = (const float*)d_in[5];
    const float* Wo   = (const float*)d_in[6];
    const float* bo   = (const float*)d_in[7];
    float* out = (float*)d_out;

    __half *qh, *kh, *vh, *oh;
    cudaGetSymbolAddress((void**)&qh, g_qh);
    cudaGetSymbolAddress((void**)&kh, g_kh);
    cudaGetSymbolAddress((void**)&vh, g_vh);
    cudaGetSymbolAddress((void**)&oh, g_oh);

    cudaFuncSetAttribute(attn_fp16,
                         cudaFuncAttributeMaxDynamicSharedMemorySize,
                         ATTN_SMEM_WORDS * (int)sizeof(unsigned));

    dim3 gblk(256);
    dim3 ggrid(Cv / 128, Mrows / 128);   // (8, 72)

    gemm_proj<<<ggrid, gblk>>>(img, Wq, qh, fcos, fsin, 0.125f);
    gemm_proj<<<ggrid, gblk>>>(img, Wk, kh, fcos, fsin, 1.0f);
    gemm_proj<<<ggrid, gblk>>>(img, Wv, vh, nullptr, nullptr, 1.0f);

    attn_fp16<<<Bv * Hv * Tv * 9, 256,
                ATTN_SMEM_WORDS * sizeof(unsigned)>>>();

    gemm_out<<<ggrid, gblk>>>(oh, Wo, out, bo);
}

// round 9
// speedup vs baseline: 2.3132x; 1.2873x over previous
#include <cuda_runtime.h>
#include <cuda_fp16.h>
#include <math.h>
#include <stdint.h>

// Problem constants
#define Bv 2
#define Tv 8
#define Nv 576
#define Cv 1024
#define Hv 16
#define HDv 64
#define TNv (Tv * Nv)       // 4608
#define Mrows (Bv * TNv)    // 9216
#define CW (Cv / 2)         // 512 uint words per token row

// Scratch (device globals — no runtime allocation allowed)
__device__ __half g_qh[(size_t)Mrows * Cv];
__device__ __half g_kh[(size_t)Mrows * Cv];
__device__ __half g_vh[(size_t)Mrows * Cv];
__device__ __half g_oh[(size_t)Mrows * Cv];
__device__ __half g_imgh[(size_t)Mrows * Cv];
__device__ __half g_wqh[(size_t)Cv * Cv];
__device__ __half g_wkh[(size_t)Cv * Cv];
__device__ __half g_wvh[(size_t)Cv * Cv];
__device__ __half g_woh[(size_t)Cv * Cv];

// ---------------------------------------------------------------------------
// fp16 helpers
// ---------------------------------------------------------------------------
__device__ __forceinline__ unsigned f2h2(float lo, float hi) {
    __half2 h = __floats2half2_rn(lo, hi);
    return *(unsigned*)&h;
}
__device__ __forceinline__ unsigned h2lows(unsigned a, unsigned b) {
    unsigned r;
    asm("prmt.b32 %0, %1, %2, 0x5410;" : "=r"(r) : "r"(a), "r"(b));
    return r;
}
__device__ __forceinline__ unsigned h2highs(unsigned a, unsigned b) {
    unsigned r;
    asm("prmt.b32 %0, %1, %2, 0x7632;" : "=r"(r) : "r"(a), "r"(b));
    return r;
}
__device__ __forceinline__ void mma16(float d[4], const unsigned a[4],
                                      const unsigned b[2]) {
    asm volatile(
        "mma.sync.aligned.m16n8k16.row.col.f32.f16.f16.f32 "
        "{%0,%1,%2,%3},{%4,%5,%6,%7},{%8,%9},{%0,%1,%2,%3};"
        : "+f"(d[0]), "+f"(d[1]), "+f"(d[2]), "+f"(d[3])
        : "r"(a[0]), "r"(a[1]), "r"(a[2]), "r"(a[3]), "r"(b[0]), "r"(b[1]));
}

// ---------------------------------------------------------------------------
// fp32 -> fp16 conversion pre-pass (8 elems/thread)
// ---------------------------------------------------------------------------
__global__ __launch_bounds__(256) void cvt_f2h(
    const float* __restrict__ s, __half* __restrict__ d, int n8)
{
    int i = blockIdx.x * blockDim.x + threadIdx.x;
    if (i >= n8) return;
    const float4* sp = (const float4*)s + (size_t)i * 2;
    float4 a = sp[0], b2 = sp[1];
    uint4 o;
    o.x = f2h2(a.x, a.y);  o.y = f2h2(a.z, a.w);
    o.z = f2h2(b2.x, b2.y); o.w = f2h2(b2.z, b2.w);
    *((uint4*)d + i) = o;
}

// ---------------------------------------------------------------------------
// Projection GEMM (A half, W half): out = half( rope?( scale * A@W^T ) )
// Proven round-7/8 core; loaders are pure uint4 copies now.
// ---------------------------------------------------------------------------
__global__ __launch_bounds__(256) void gemm_proj(
    const __half* __restrict__ Ah, const __half* __restrict__ Wh,
    __half* __restrict__ Out,
    const float* __restrict__ fcos, const float* __restrict__ fsin,
    float scale)
{
    __shared__ unsigned As[16 * 136];
    __shared__ unsigned Bs[16 * 136];

    const int t = threadIdx.x;
    const int lane = t & 31;
    const int w = t >> 5;
    const int gid = lane >> 2, tig = lane & 3;
    const int wm = (w >> 2) * 64, wn = (w & 3) * 32;
    const int m0 = blockIdx.y * 128, n0 = blockIdx.x * 128;

    const int row0 = t >> 2;
    const int kq = (t & 3) * 4;
    const int cstS = (t & 3) << 3;
    const int kw = (t & 3) * 4;

    const unsigned* Ap0 = (const unsigned*)Ah + (size_t)(m0 + row0) * CW + kw;
    const unsigned* Ap1 = (const unsigned*)Ah + (size_t)(m0 + 64 + row0) * CW + kw;
    const unsigned* Wp0 = (const unsigned*)Wh + (size_t)(n0 + row0) * CW + kw;
    const unsigned* Wp1 = (const unsigned*)Wh + (size_t)(n0 + 64 + row0) * CW + kw;

    float acc[4][4][4];
#pragma unroll
    for (int mt = 0; mt < 4; mt++)
#pragma unroll
        for (int nt = 0; nt < 4; nt++)
#pragma unroll
            for (int r = 0; r < 4; r++) acc[mt][nt][r] = 0.0f;

    uint4 xa = *(const uint4*)Ap0;
    uint4 ya = *(const uint4*)Ap1;
    uint4 za = *(const uint4*)Wp0;
    uint4 ua = *(const uint4*)Wp1;

    for (int ch = 0; ch < 32; ch++) {
        __syncthreads();
        {
            unsigned a0[4] = {xa.x, xa.y, xa.z, xa.w};
            unsigned a1[4] = {ya.x, ya.y, ya.z, ya.w};
            unsigned b0[4] = {za.x, za.y, za.z, za.w};
            unsigned b1[4] = {ua.x, ua.y, ua.z, ua.w};
#pragma unroll
            for (int jj = 0; jj < 4; jj++) {
                int kr = (kq + jj) * 136;
                As[kr + (row0 ^ cstS)]        = a0[jj];
                As[kr + ((row0 + 64) ^ cstS)] = a1[jj];
                Bs[kr + (row0 ^ cstS)]        = b0[jj];
                Bs[kr + ((row0 + 64) ^ cstS)] = b1[jj];
            }
        }
        __syncthreads();
        if (ch + 1 < 32) {
            const int kc = (ch + 1) * 16;
            xa = *(const uint4*)(Ap0 + kc);
            ya = *(const uint4*)(Ap1 + kc);
            za = *(const uint4*)(Wp0 + kc);
            ua = *(const uint4*)(Wp1 + kc);
        }
#pragma unroll
        for (int s = 0; s < 2; s++) {
            const int kbp = s * 8;
            const int c0 = (((kbp + tig) >> 2) & 3) << 3;
            const int c1 = (((kbp + tig + 4) >> 2) & 3) << 3;
            const int kr0 = (kbp + tig) * 136;
            const int kr1 = (kbp + tig + 4) * 136;
            unsigned a[4][4], bb[4][2];
#pragma unroll
            for (int mt = 0; mt < 4; mt++) {
                int m = wm + mt * 16 + gid;
                a[mt][0] = As[kr0 + (m ^ c0)];
                a[mt][1] = As[kr0 + ((m + 8) ^ c0)];
                a[mt][2] = As[kr1 + (m ^ c1)];
                a[mt][3] = As[kr1 + ((m + 8) ^ c1)];
            }
#pragma unroll
            for (int nt = 0; nt < 4; nt++) {
                int n = wn + nt * 8 + gid;
                bb[nt][0] = Bs[kr0 + (n ^ c0)];
                bb[nt][1] = Bs[kr1 + (n ^ c1)];
            }
#pragma unroll
            for (int mt = 0; mt < 4; mt++)
#pragma unroll
                for (int nt = 0; nt < 4; nt++)
                    mma16(acc[mt][nt], a[mt], bb[nt]);
        }
    }

    const bool rope = (fcos != nullptr);
#pragma unroll
    for (int mt = 0; mt < 4; mt++) {
        const int r = m0 + wm + mt * 16 + gid;
        const int r8 = r + 8;
        const int s_lo = (r  >= TNv) ? r  - TNv : r;
        const int s_hi = (r8 >= TNv) ? r8 - TNv : r8;
#pragma unroll
        for (int nt = 0; nt < 4; nt++) {
            const int c = n0 + wn + nt * 8 + tig * 2;
            float a0 = acc[mt][nt][0] * scale;
            float a1 = acc[mt][nt][1] * scale;
            float a2 = acc[mt][nt][2] * scale;
            float a3 = acc[mt][nt][3] * scale;
            if (rope) {
                const int d = c & 63;
                float2 cl = *(const float2*)(fcos + (size_t)s_lo * HDv + d);
                float2 sl = *(const float2*)(fsin + (size_t)s_lo * HDv + d);
                float2 chh = *(const float2*)(fcos + (size_t)s_hi * HDv + d);
                float2 sh = *(const float2*)(fsin + (size_t)s_hi * HDv + d);
                float y0 = a0 * cl.x - a1 * sl.x;
                float y1 = a1 * cl.y + a0 * sl.y;
                float y2 = a2 * chh.x - a3 * sh.x;
                float y3 = a3 * chh.y + a2 * sh.y;
                a0 = y0; a1 = y1; a2 = y2; a3 = y3;
            }
            *(unsigned*)(Out + (size_t)r  * Cv + c) = f2h2(a0, a1);
            *(unsigned*)(Out + (size_t)r8 * Cv + c) = f2h2(a2, a3);
        }
    }
}

// ---------------------------------------------------------------------------
// Output GEMM (A half, W half): out fp32 = A@W^T + bias
// ---------------------------------------------------------------------------
__global__ __launch_bounds__(256) void gemm_out(
    const __half* __restrict__ Ah, const __half* __restrict__ Wh,
    float* __restrict__ Cout, const float* __restrict__ bias)
{
    __shared__ unsigned As[16 * 136];
    __shared__ unsigned Bs[16 * 136];

    const int t = threadIdx.x;
    const int lane = t & 31;
    const int w = t >> 5;
    const int gid = lane >> 2, tig = lane & 3;
    const int wm = (w >> 2) * 64, wn = (w & 3) * 32;
    const int m0 = blockIdx.y * 128, n0 = blockIdx.x * 128;

    const int row0 = t >> 2;
    const int kq = (t & 3) * 4;
    const int cstS = (t & 3) << 3;
    const int kw = (t & 3) * 4;

    const unsigned* Ap0 = (const unsigned*)Ah + (size_t)(m0 + row0) * CW + kw;
    const unsigned* Ap1 = (const unsigned*)Ah + (size_t)(m0 + 64 + row0) * CW + kw;
    const unsigned* Wp0 = (const unsigned*)Wh + (size_t)(n0 + row0) * CW + kw;
    const unsigned* Wp1 = (const unsigned*)Wh + (size_t)(n0 + 64 + row0) * CW + kw;

    float acc[4][4][4];
#pragma unroll
    for (int mt = 0; mt < 4; mt++)
#pragma unroll
        for (int nt = 0; nt < 4; nt++)
#pragma unroll
            for (int r = 0; r < 4; r++) acc[mt][nt][r] = 0.0f;

    uint4 xa = *(const uint4*)Ap0;
    uint4 ya = *(const uint4*)Ap1;
    uint4 za = *(const uint4*)Wp0;
    uint4 ua = *(const uint4*)Wp1;

    for (int ch = 0; ch < 32; ch++) {
        __syncthreads();
        {
            unsigned a0[4] = {xa.x, xa.y, xa.z, xa.w};
            unsigned a1[4] = {ya.x, ya.y, ya.z, ya.w};
            unsigned b0[4] = {za.x, za.y, za.z, za.w};
            unsigned b1[4] = {ua.x, ua.y, ua.z, ua.w};
#pragma unroll
            for (int jj = 0; jj < 4; jj++) {
                int kr = (kq + jj) * 136;
                As[kr + (row0 ^ cstS)]        = a0[jj];
                As[kr + ((row0 + 64) ^ cstS)] = a1[jj];
                Bs[kr + (row0 ^ cstS)]        = b0[jj];
                Bs[kr + ((row0 + 64) ^ cstS)] = b1[jj];
            }
        }
        __syncthreads();
        if (ch + 1 < 32) {
            const int kc = (ch + 1) * 16;
            xa = *(const uint4*)(Ap0 + kc);
            ya = *(const uint4*)(Ap1 + kc);
            za = *(const uint4*)(Wp0 + kc);
            ua = *(const uint4*)(Wp1 + kc);
        }
#pragma unroll
        for (int s = 0; s < 2; s++) {
            const int kbp = s * 8;
            const int c0 = (((kbp + tig) >> 2) & 3) << 3;
            const int c1 = (((kbp + tig + 4) >> 2) & 3) << 3;
            const int kr0 = (kbp + tig) * 136;
            const int kr1 = (kbp + tig + 4) * 136;
            unsigned a[4][4], bb[4][2];
#pragma unroll
            for (int mt = 0; mt < 4; mt++) {
                int m = wm + mt * 16 + gid;
                a[mt][0] = As[kr0 + (m ^ c0)];
                a[mt][1] = As[kr0 + ((m + 8) ^ c0)];
                a[mt][2] = As[kr1 + (m ^ c1)];
                a[mt][3] = As[kr1 + ((m + 8) ^ c1)];
            }
#pragma unroll
            for (int nt = 0; nt < 4; nt++) {
                int n = wn + nt * 8 + gid;
                bb[nt][0] = Bs[kr0 + (n ^ c0)];
                bb[nt][1] = Bs[kr1 + (n ^ c1)];
            }
#pragma unroll
            for (int mt = 0; mt < 4; mt++)
#pragma unroll
                for (int nt = 0; nt < 4; nt++)
                    mma16(acc[mt][nt], a[mt], bb[nt]);
        }
    }

#pragma unroll
    for (int mt = 0; mt < 4; mt++) {
        int r = m0 + wm + mt * 16 + gid;
#pragma unroll
        for (int nt = 0; nt < 4; nt++) {
            int c = n0 + wn + nt * 8 + tig * 2;
            float b0v = bias[c], b1v = bias[c + 1];
            float2 v0, v1;
            v0.x = acc[mt][nt][0] + b0v;
            v0.y = acc[mt][nt][1] + b1v;
            v1.x = acc[mt][nt][2] + b0v;
            v1.y = acc[mt][nt][3] + b1v;
            *(float2*)(Cout + (size_t)r * Cv + c) = v0;
            *(float2*)(Cout + (size_t)(r + 8) * Cv + c) = v1;
        }
    }
}

// ---------------------------------------------------------------------------
// Flash attention, fp16. Q fragments pinned in registers (loop-invariant);
// K/V register-prefetched; Qs smem region removed (20.2 KB total).
// Ks: [kp(32)][col] stride 72;  Ps: [keyp(32)][q] stride 72
// Vs: [keyp(32)][d] stride 72 (half2 = (key even, key odd))
// ---------------------------------------------------------------------------
#define KS_OFF 0
#define VS_OFF 2304
#define PS_OFF 4608
#define RED_OFF 6912
#define MR_OFF 7168
#define LR_OFF 7232
#define AR_OFF 7296
#define ATTN_SMEM_WORDS 7360

__global__ __launch_bounds__(256) void attn_fp16()
{
    extern __shared__ unsigned usm[];
    unsigned* Ks = usm + KS_OFF;
    unsigned* Vs = usm + VS_OFF;
    unsigned* Ps = usm + PS_OFF;
    float* red  = (float*)(usm + RED_OFF);
    float* Mrow = (float*)(usm + MR_OFF);
    float* Lrow = (float*)(usm + LR_OFF);
    float* Arow = (float*)(usm + AR_OFF);

    const int bx = blockIdx.x;
    const int nb = bx % 9;
    const int tt = (bx / 9) % Tv;
    const int hh = (bx / (9 * Tv)) % Hv;
    const int b  = bx / (9 * Tv * Hv);
    const int tprev = (tt == 0) ? 1 : tt - 1;
    const int tnext = (tt == Tv - 1) ? Tv - 2 : tt + 1;

    const int t = threadIdx.x;
    const int lane = t & 31;
    const int w = t >> 5;
    const int gid = lane >> 2, tig = lane & 3;
    const int wm = w >> 2, wn = w & 3;

    const int lrow = t >> 2;
    const int dc = (t & 3) * 16;
    const int cstL = (t & 3) << 3;
    const int kp0 = dc >> 1;

    const int vp = t >> 3;
    const int vd = (t & 7) * 4;

    // ---- stage Q via Ks buffer, pin fragments in registers ----
    {
        const unsigned* qb = (const unsigned*)g_qh +
            (size_t)(b * TNv + tt * Nv + nb * 64 + lrow) * CW + hh * 32 + kp0;
        uint4 u0 = *(const uint4*)qb;
        uint4 u1 = *(const uint4*)(qb + 4);
        const int cq = lrow ^ cstL;
        Ks[(kp0 + 0) * 72 + cq] = u0.x;
        Ks[(kp0 + 1) * 72 + cq] = u0.y;
        Ks[(kp0 + 2) * 72 + cq] = u0.z;
        Ks[(kp0 + 3) * 72 + cq] = u0.w;
        Ks[(kp0 + 4) * 72 + cq] = u1.x;
        Ks[(kp0 + 5) * 72 + cq] = u1.y;
        Ks[(kp0 + 6) * 72 + cq] = u1.z;
        Ks[(kp0 + 7) * 72 + cq] = u1.w;
    }
    __syncthreads();
    unsigned qa[4][2][4];
#pragma unroll
    for (int st = 0; st < 4; st++) {
        const int cs = (st & 3) << 3;
        const int kr0 = (st * 8 + tig) * 72;
        const int kr1 = (st * 8 + tig + 4) * 72;
#pragma unroll
        for (int mi = 0; mi < 2; mi++) {
            int q0 = wm * 32 + mi * 16 + gid;
            qa[st][mi][0] = Ks[kr0 + (q0 ^ cs)];
            qa[st][mi][1] = Ks[kr0 + ((q0 + 8) ^ cs)];
            qa[st][mi][2] = Ks[kr1 + (q0 ^ cs)];
            qa[st][mi][3] = Ks[kr1 + ((q0 + 8) ^ cs)];
        }
    }
    if (t < 64) { Mrow[t] = -1e30f; Lrow[t] = 0.0f; }

    float o[2][2][4];
#pragma unroll
    for (int mi = 0; mi < 2; mi++)
#pragma unroll
        for (int nj = 0; nj < 2; nj++)
#pragma unroll
            for (int r = 0; r < 4; r++) o[mi][nj][r] = 0.0f;

    // K/V register prefetch state
    uint4 ku0, ku1;
    uint2 vA0, vB0, vA1, vB1;
    {
        const size_t tokbase = (size_t)(b * TNv + tprev * Nv);  // tile 0: nk0=0
        const unsigned* kb_ = (const unsigned*)g_kh +
            (tokbase + lrow) * CW + hh * 32 + kp0;
        ku0 = *(const uint4*)kb_;
        ku1 = *(const uint4*)(kb_ + 4);
        const unsigned* va = (const unsigned*)g_vh +
            (tokbase + 2 * vp) * CW + hh * 32 + (vd >> 1);
        const unsigned* vb2 = va + CW;
        vA0 = *(const uint2*)va;  vB0 = *(const uint2*)vb2;
        vA1 = *(const uint2*)(va + 16); vB1 = *(const uint2*)(vb2 + 16);
    }

    for (int kt = 0; kt < 18; kt++) {
        __syncthreads();   // prior tile's reads of Ks/Vs/Ps complete
        // store prefetched K/V regs to smem
        {
            const int ck = lrow ^ cstL;
            Ks[(kp0 + 0) * 72 + ck] = ku0.x;
            Ks[(kp0 + 1) * 72 + ck] = ku0.y;
            Ks[(kp0 + 2) * 72 + ck] = ku0.z;
            Ks[(kp0 + 3) * 72 + ck] = ku0.w;
            Ks[(kp0 + 4) * 72 + ck] = ku1.x;
            Ks[(kp0 + 5) * 72 + ck] = ku1.y;
            Ks[(kp0 + 6) * 72 + ck] = ku1.z;
            Ks[(kp0 + 7) * 72 + ck] = ku1.w;
            unsigned* vr = &Vs[vp * 72 + vd];
            vr[0] = h2lows(vA0.x, vB0.x);
            vr[1] = h2highs(vA0.x, vB0.x);
            vr[2] = h2lows(vA0.y, vB0.y);
            vr[3] = h2highs(vA0.y, vB0.y);
            vr[32] = h2lows(vA1.x, vB1.x);
            vr[33] = h2highs(vA1.x, vB1.x);
            vr[34] = h2lows(vA1.y, vB1.y);
            vr[35] = h2highs(vA1.y, vB1.y);
        }
        __syncthreads();
        // prefetch next tile (overlaps compute below)
        if (kt + 1 < 18) {
            const int kt2 = kt + 1;
            const int tsrc = (kt2 < 9) ? tprev : tnext;
            const int nk0 = (kt2 % 9) * 64;
            const size_t tokbase = (size_t)(b * TNv + tsrc * Nv + nk0);
            const unsigned* kb_ = (const unsigned*)g_kh +
                (tokbase + lrow) * CW + hh * 32 + kp0;
            ku0 = *(const uint4*)kb_;
            ku1 = *(const uint4*)(kb_ + 4);
            const unsigned* va = (const unsigned*)g_vh +
                (tokbase + 2 * vp) * CW + hh * 32 + (vd >> 1);
            const unsigned* vb2 = va + CW;
            vA0 = *(const uint2*)va;  vB0 = *(const uint2*)vb2;
            vA1 = *(const uint2*)(va + 16); vB1 = *(const uint2*)(vb2 + 16);
        }

        // ---- S = Q @ K^T (Q from registers) ----
        float s[2][2][4];
#pragma unroll
        for (int mi = 0; mi < 2; mi++)
#pragma unroll
            for (int ni = 0; ni < 2; ni++)
#pragma unroll
                for (int r = 0; r < 4; r++) s[mi][ni][r] = 0.0f;
#pragma unroll
        for (int st = 0; st < 4; st++) {
            const int cs = (st & 3) << 3;
            const int kr0 = (st * 8 + tig) * 72;
            const int kr1 = (st * 8 + tig + 4) * 72;
            unsigned bb[2][2];
#pragma unroll
            for (int ni = 0; ni < 2; ni++) {
                int kc = wn * 16 + ni * 8 + gid;
                bb[ni][0] = Ks[kr0 + (kc ^ cs)];
                bb[ni][1] = Ks[kr1 + (kc ^ cs)];
            }
#pragma unroll
            for (int mi = 0; mi < 2; mi++)
#pragma unroll
                for (int ni = 0; ni < 2; ni++)
                    mma16(s[mi][ni], qa[st][mi], bb[ni]);
        }

        // ---- row max -> block reduce ----
#pragma unroll
        for (int mi = 0; mi < 2; mi++)
#pragma unroll
            for (int h2 = 0; h2 < 2; h2++) {
                float mx = fmaxf(fmaxf(s[mi][0][h2 * 2], s[mi][0][h2 * 2 + 1]),
                                 fmaxf(s[mi][1][h2 * 2], s[mi][1][h2 * 2 + 1]));
                mx = fmaxf(mx, __shfl_xor_sync(0xffffffffu, mx, 1));
                mx = fmaxf(mx, __shfl_xor_sync(0xffffffffu, mx, 2));
                if (tig == 0)
                    red[wn * 64 + wm * 32 + mi * 16 + h2 * 8 + gid] = mx;
            }
        __syncthreads();
        if (t < 64) {
            float tm = fmaxf(fmaxf(red[t], red[64 + t]),
                             fmaxf(red[128 + t], red[192 + t]));
            float mold = Mrow[t];
            float mnew = fmaxf(mold, tm);
            Mrow[t] = mnew;
            Arow[t] = __expf(mold - mnew);
        }
        __syncthreads();

        // ---- p = exp(s-m), stage P, sums, rescale O ----
        const int cp = wn << 3;
        const int kp1 = wn * 8 + tig;
        const int kp2 = kp1 + 4;
#pragma unroll
        for (int mi = 0; mi < 2; mi++)
#pragma unroll
            for (int h2 = 0; h2 < 2; h2++) {
                int r = wm * 32 + mi * 16 + h2 * 8 + gid;
                float mrow = Mrow[r];
                float al = Arow[r];
                float p0 = __expf(s[mi][0][h2 * 2]     - mrow);
                float p1 = __expf(s[mi][0][h2 * 2 + 1] - mrow);
                float p2 = __expf(s[mi][1][h2 * 2]     - mrow);
                float p3 = __expf(s[mi][1][h2 * 2 + 1] - mrow);
                float rs = p0 + p1 + p2 + p3;
                rs += __shfl_xor_sync(0xffffffffu, rs, 1);
                rs += __shfl_xor_sync(0xffffffffu, rs, 2);
                if (tig == 0) red[wn * 64 + r] = rs;
                int rq = r ^ cp;
                Ps[kp1 * 72 + rq] = f2h2(p0, p1);
                Ps[kp2 * 72 + rq] = f2h2(p2, p3);
                o[mi][0][h2 * 2]     *= al;
                o[mi][0][h2 * 2 + 1] *= al;
                o[mi][1][h2 * 2]     *= al;
                o[mi][1][h2 * 2 + 1] *= al;
            }
        __syncthreads();
        if (t < 64)
            Lrow[t] = Lrow[t] * Arow[t] +
                      red[t] + red[64 + t] + red[128 + t] + red[192 + t];

        // ---- O += P @ V ----
#pragma unroll
        for (int st = 0; st < 4; st++) {
            const int cs = (st & 3) << 3;
            const int kr0 = (st * 8 + tig) * 72;
            const int kr1 = (st * 8 + tig + 4) * 72;
            unsigned a[2][4], bb[2][2];
#pragma unroll
            for (int mi = 0; mi < 2; mi++) {
                int q0 = wm * 32 + mi * 16 + gid;
                a[mi][0] = Ps[kr0 + (q0 ^ cs)];
                a[mi][1] = Ps[kr0 + ((q0 + 8) ^ cs)];
                a[mi][2] = Ps[kr1 + (q0 ^ cs)];
                a[mi][3] = Ps[kr1 + ((q0 + 8) ^ cs)];
            }
#pragma unroll
            for (int nj = 0; nj < 2; nj++) {
                int dcol = wn * 16 + nj * 8 + gid;
                bb[nj][0] = Vs[kr0 + dcol];
                bb[nj][1] = Vs[kr1 + dcol];
            }
#pragma unroll
            for (int mi = 0; mi < 2; mi++)
#pragma unroll
                for (int nj = 0; nj < 2; nj++)
                    mma16(o[mi][nj], a[mi], bb[nj]);
        }
    }

    __syncthreads();
#pragma unroll
    for (int mi = 0; mi < 2; mi++)
#pragma unroll
        for (int h2 = 0; h2 < 2; h2++) {
            int r = wm * 32 + mi * 16 + h2 * 8 + gid;
            float inv = 1.0f / Lrow[r];
            size_t token = (size_t)(b * TNv + tt * Nv + nb * 64 + r);
            __half* ob = g_oh + token * Cv + hh * HDv;
#pragma unroll
            for (int nj = 0; nj < 2; nj++) {
                int dcol = wn * 16 + nj * 8 + tig * 2;
                *(unsigned*)(ob + dcol) =
                    f2h2(o[mi][nj][h2 * 2] * inv, o[mi][nj][h2 * 2 + 1] * inv);
            }
        }
}

// ---------------------------------------------------------------------------
// Launch
// ---------------------------------------------------------------------------
extern "C" void kernel_launch(void* const* d_in, const int* in_sizes, int n_in,
                              void* d_out, int out_size)
{
    (void)in_sizes; (void)n_in; (void)out_size;
    const float* img  = (const float*)d_in[0];
    const float* fcos = (const float*)d_in[1];
    const float* fsin = (const float*)d_in[2];
    const float* Wq   = (const float*)d_in[3];
    const float* Wk   = (const float*)d_in[4];
    const float* Wv   = (const float*)d_in[5];
    const float* Wo   = (const float*)d_in[6];
    const float* bo   = (const float*)d_in[7];
    float* out = (float*)d_out;

    __half *qh, *kh, *vh, *oh, *imgh, *wqh, *wkh, *wvh, *woh;
    cudaGetSymbolAddress((void**)&qh, g_qh);
    cudaGetSymbolAddress((void**)&kh, g_kh);
    cudaGetSymbolAddress((void**)&vh, g_vh);
    cudaGetSymbolAddress((void**)&oh, g_oh);
    cudaGetSymbolAddress((void**)&imgh, g_imgh);
    cudaGetSymbolAddress((void**)&wqh, g_wqh);
    cudaGetSymbolAddress((void**)&wkh, g_wkh);
    cudaGetSymbolAddress((void**)&wvh, g_wvh);
    cudaGetSymbolAddress((void**)&woh, g_woh);

    cudaFuncSetAttribute(attn_fp16,
                         cudaFuncAttributeMaxDynamicSharedMemorySize,
                         ATTN_SMEM_WORDS * (int)sizeof(unsigned));

    // pre-pass: fp32 -> fp16 once for img + all weights
    const int imgN8 = (int)((size_t)Mrows * Cv / 8);   // 1179648
    const int wN8 = (int)((size_t)Cv * Cv / 8);        // 131072
    cvt_f2h<<<(imgN8 + 255) / 256, 256>>>(img, imgh, imgN8);
    cvt_f2h<<<(wN8 + 255) / 256, 256>>>(Wq, wqh, wN8);
    cvt_f2h<<<(wN8 + 255) / 256, 256>>>(Wk, wkh, wN8);
    cvt_f2h<<<(wN8 + 255) / 256, 256>>>(Wv, wvh, wN8);
    cvt_f2h<<<(wN8 + 255) / 256, 256>>>(Wo, woh, wN8);

    dim3 gblk(256);
    dim3 ggrid(Cv / 128, Mrows / 128);   // (8, 72)

    gemm_proj<<<ggrid, gblk>>>(imgh, wqh, qh, fcos, fsin, 0.125f);
    gemm_proj<<<ggrid, gblk>>>(imgh, wkh, kh, fcos, fsin, 1.0f);
    gemm_proj<<<ggrid, gblk>>>(imgh, wvh, vh, nullptr, nullptr, 1.0f);

    attn_fp16<<<Bv * Hv * Tv * 9, 256,
                ATTN_SMEM_WORDS * sizeof(unsigned)>>>();

    gemm_out<<<ggrid, gblk>>>(oh, woh, out, bo);
}